// round 3
// baseline (speedup 1.0000x reference)
#include <cuda_runtime.h>
#include <cstddef>

#define DIM     768
#define HEADS   12
#define HD      64
#define RR      64
#define BB      2
#define NSEQ    4096
#define CHUNK   1024
#define NCHUNKS 4
#define TOKENS  (BB*NSEQ)     // 8192
#define QKV_DIM (3*DIM)       // 2304
#define LSCALE  2.0f          // 128 / 64
#define ATT_SCALE 0.125f      // 64^-0.5

// ------------------------------------------------------------------ scratch
__device__ float g_qkv[(size_t)TOKENS * QKV_DIM];  // 75.5 MB: q|k|v per token
__device__ float g_h  [(size_t)TOKENS * RR];       // x @ Aqkv[e]^T
__device__ float g_o  [(size_t)TOKENS * DIM];      // attention output
__device__ float g_h2 [(size_t)TOKENS * RR];       // o @ Aproj[e]^T

// expert index helper: estride=1 -> int32 array, estride=2 -> int64 viewed
// as int32 words (little-endian low word carries the value).
__device__ __forceinline__ int expert_of(const int* ex, int chunk, int estride) {
    return ex[chunk * estride];
}

// ------------------------------------------------------ small LoRA-A GEMM
// C[M x 64] = A[M x 768] @ W_e[64 x 768]^T, W per-expert (stride 64*768)
__global__ void __launch_bounds__(256) lora_h_kernel(
    const float* __restrict__ A, const float* __restrict__ Wbase,
    float* __restrict__ C, const int* __restrict__ experts, int estride)
{
    const int m0 = blockIdx.x * 64;
    const int e  = expert_of(experts, (m0 % NSEQ) / CHUNK, estride);
    const float* W = Wbase + (size_t)e * RR * DIM;

    __shared__ float As[16][65];
    __shared__ float Bs[16][65];

    const int tid = threadIdx.x;
    const int tx  = tid & 15;
    const int ty  = tid >> 4;

    float acc[4][4] = {};

    for (int k0 = 0; k0 < DIM; k0 += 16) {
        #pragma unroll
        for (int l = 0; l < 4; l++) {
            int idx = tid + l * 256;          // 0..1023
            int row = idx >> 4;
            int kk  = idx & 15;
            As[kk][row] = A[(size_t)(m0 + row) * DIM + k0 + kk];
            Bs[kk][row] = W[(size_t)row * DIM + k0 + kk];
        }
        __syncthreads();
        #pragma unroll
        for (int kk = 0; kk < 16; kk++) {
            float a[4], b[4];
            #pragma unroll
            for (int i = 0; i < 4; i++) a[i] = As[kk][ty * 4 + i];
            #pragma unroll
            for (int j = 0; j < 4; j++) b[j] = Bs[kk][tx * 4 + j];
            #pragma unroll
            for (int i = 0; i < 4; i++)
                #pragma unroll
                for (int j = 0; j < 4; j++) acc[i][j] += a[i] * b[j];
        }
        __syncthreads();
    }
    #pragma unroll
    for (int i = 0; i < 4; i++)
        #pragma unroll
        for (int j = 0; j < 4; j++)
            C[(size_t)(m0 + ty * 4 + i) * RR + tx * 4 + j] = acc[i][j];
}

// ---------------------------------------------- fused main GEMM (+LoRA B)
// C[M x N] = A[M x 768] @ W[N x 768]^T + LSCALE * Hm[M x 64] @ Bl_e[N x 64]^T
// Tile 128x128, 256 threads, 8x8 per thread.
__global__ void __launch_bounds__(256, 2) gemm_fused128(
    const float* __restrict__ A,  const float* __restrict__ W,
    const float* __restrict__ Hm, const float* __restrict__ Blora,
    float* __restrict__ C, int N, const int* __restrict__ experts, int estride)
{
    const int m0 = blockIdx.y * 128;
    const int n0 = blockIdx.x * 128;
    const int e  = expert_of(experts, (m0 % NSEQ) / CHUNK, estride);

    __shared__ float As[16][132];
    __shared__ float Bs[16][132];

    const int tid = threadIdx.x;
    const int tx  = tid & 15;
    const int ty  = tid >> 4;

    float acc[8][8] = {};

    // main K = 768
    for (int k0 = 0; k0 < DIM; k0 += 16) {
        #pragma unroll
        for (int l = 0; l < 2; l++) {
            int idx = tid + l * 256;          // 0..511 float4 slots
            int row = idx >> 2;
            int k4  = (idx & 3) * 4;
            float4 av = *(const float4*)(A + (size_t)(m0 + row) * DIM + k0 + k4);
            float4 bv = *(const float4*)(W + (size_t)(n0 + row) * DIM + k0 + k4);
            As[k4 + 0][row] = av.x; As[k4 + 1][row] = av.y;
            As[k4 + 2][row] = av.z; As[k4 + 3][row] = av.w;
            Bs[k4 + 0][row] = bv.x; Bs[k4 + 1][row] = bv.y;
            Bs[k4 + 2][row] = bv.z; Bs[k4 + 3][row] = bv.w;
        }
        __syncthreads();
        #pragma unroll
        for (int kk = 0; kk < 16; kk++) {
            float a[8], b[8];
            #pragma unroll
            for (int i = 0; i < 8; i++) a[i] = As[kk][ty * 8 + i];
            #pragma unroll
            for (int j = 0; j < 8; j++) b[j] = Bs[kk][tx * 8 + j];
            #pragma unroll
            for (int i = 0; i < 8; i++)
                #pragma unroll
                for (int j = 0; j < 8; j++) acc[i][j] += a[i] * b[j];
        }
        __syncthreads();
    }

    // LoRA K = 64 (A-side values pre-scaled by LSCALE)
    {
        const float* Bw = Blora + (size_t)e * N * RR;
        for (int k0 = 0; k0 < RR; k0 += 16) {
            #pragma unroll
            for (int l = 0; l < 2; l++) {
                int idx = tid + l * 256;
                int row = idx >> 2;
                int k4  = (idx & 3) * 4;
                float4 av = *(const float4*)(Hm + (size_t)(m0 + row) * RR + k0 + k4);
                float4 bv = *(const float4*)(Bw + (size_t)(n0 + row) * RR + k0 + k4);
                As[k4 + 0][row] = av.x * LSCALE; As[k4 + 1][row] = av.y * LSCALE;
                As[k4 + 2][row] = av.z * LSCALE; As[k4 + 3][row] = av.w * LSCALE;
                Bs[k4 + 0][row] = bv.x; Bs[k4 + 1][row] = bv.y;
                Bs[k4 + 2][row] = bv.z; Bs[k4 + 3][row] = bv.w;
            }
            __syncthreads();
            #pragma unroll
            for (int kk = 0; kk < 16; kk++) {
                float a[8], b[8];
                #pragma unroll
                for (int i = 0; i < 8; i++) a[i] = As[kk][ty * 8 + i];
                #pragma unroll
                for (int j = 0; j < 8; j++) b[j] = Bs[kk][tx * 8 + j];
                #pragma unroll
                for (int i = 0; i < 8; i++)
                    #pragma unroll
                    for (int j = 0; j < 8; j++) acc[i][j] += a[i] * b[j];
            }
            __syncthreads();
        }
    }

    #pragma unroll
    for (int i = 0; i < 8; i++) {
        size_t row = (size_t)(m0 + ty * 8 + i);
        #pragma unroll
        for (int j4 = 0; j4 < 2; j4++) {
            float4 v;
            v.x = acc[i][j4 * 4 + 0]; v.y = acc[i][j4 * 4 + 1];
            v.z = acc[i][j4 * 4 + 2]; v.w = acc[i][j4 * 4 + 3];
            *(float4*)(C + row * N + n0 + tx * 8 + j4 * 4) = v;
        }
    }
}

// -------------------------------------------------------- flash attention
// grid: (q-tiles per chunk = 8, B*HEADS = 24, NCHUNKS = 4)
// 256 threads: lane group of 4 splits HD=64 into 16-wide slices; each thread
// owns 2 query rows. Keys streamed through smem in 32-key tiles; online
// softmax per 8-key subtile; partial dots reduced with shfl_xor(1|2).
#define BQ 128
#define BK 32

__global__ void __launch_bounds__(256, 2) attn_kernel(
    const float* __restrict__ qkv, float* __restrict__ outp)
{
    __shared__ float ks[BK][HD];
    __shared__ float vs[BK][HD];

    const int qt    = blockIdx.x;           // 0..7
    const int b     = blockIdx.y / HEADS;
    const int h     = blockIdx.y % HEADS;
    const int chunk = blockIdx.z;
    const int tid   = threadIdx.x;
    const int part  = tid & 3;              // 16-wide d-slice
    const int qg    = tid >> 2;             // 0..63
    const int kl    = (chunk + 1) * CHUNK;  // keys visible to this chunk

    float qf[2][16];
    float of[2][16] = {};
    float mrow[2] = { -1e30f, -1e30f };
    float lrow[2] = { 0.f, 0.f };

    #pragma unroll
    for (int r = 0; r < 2; r++) {
        int n = chunk * CHUNK + qt * BQ + qg * 2 + r;
        const float* qp = qkv + ((size_t)(b * NSEQ + n)) * QKV_DIM + h * HD + part * 16;
        #pragma unroll
        for (int c = 0; c < 4; c++) {
            float4 v = *(const float4*)(qp + c * 4);
            qf[r][c * 4 + 0] = v.x * ATT_SCALE;
            qf[r][c * 4 + 1] = v.y * ATT_SCALE;
            qf[r][c * 4 + 2] = v.z * ATT_SCALE;
            qf[r][c * 4 + 3] = v.w * ATT_SCALE;
        }
    }

    for (int kt = 0; kt < kl; kt += BK) {
        #pragma unroll
        for (int l4 = 0; l4 < 2; l4++) {
            int idx = tid + l4 * 256;       // 0..511 float4 slots
            int row = idx >> 4;
            int c4  = (idx & 15) * 4;
            size_t base = ((size_t)(b * NSEQ + kt + row)) * QKV_DIM + h * HD + c4;
            *(float4*)&ks[row][c4] = *(const float4*)(qkv + base + DIM);
            *(float4*)&vs[row][c4] = *(const float4*)(qkv + base + 2 * DIM);
        }
        __syncthreads();

        #pragma unroll
        for (int sub = 0; sub < BK; sub += 8) {
            float s[2][8];
            #pragma unroll
            for (int kk = 0; kk < 8; kk++) {
                float kr[16];
                #pragma unroll
                for (int c = 0; c < 4; c++) {
                    float4 v = *(const float4*)&ks[sub + kk][part * 16 + c * 4];
                    kr[c * 4 + 0] = v.x; kr[c * 4 + 1] = v.y;
                    kr[c * 4 + 2] = v.z; kr[c * 4 + 3] = v.w;
                }
                #pragma unroll
                for (int r = 0; r < 2; r++) {
                    float a = 0.f;
                    #pragma unroll
                    for (int j = 0; j < 16; j++) a += qf[r][j] * kr[j];
                    s[r][kk] = a;
                }
            }
            // reduce partial dots across the 4 d-slice lanes
            #pragma unroll
            for (int r = 0; r < 2; r++)
                #pragma unroll
                for (int kk = 0; kk < 8; kk++) {
                    s[r][kk] += __shfl_xor_sync(0xffffffffu, s[r][kk], 1);
                    s[r][kk] += __shfl_xor_sync(0xffffffffu, s[r][kk], 2);
                }
            // online softmax update
            #pragma unroll
            for (int r = 0; r < 2; r++) {
                float mt = s[r][0];
                #pragma unroll
                for (int kk = 1; kk < 8; kk++) mt = fmaxf(mt, s[r][kk]);
                float mn   = fmaxf(mrow[r], mt);
                float corr = __expf(mrow[r] - mn);
                mrow[r] = mn;
                lrow[r] *= corr;
                #pragma unroll
                for (int j = 0; j < 16; j++) of[r][j] *= corr;
                #pragma unroll
                for (int kk = 0; kk < 8; kk++) {
                    s[r][kk] = __expf(s[r][kk] - mn);
                    lrow[r] += s[r][kk];
                }
            }
            // P @ V
            #pragma unroll
            for (int kk = 0; kk < 8; kk++) {
                float vr[16];
                #pragma unroll
                for (int c = 0; c < 4; c++) {
                    float4 v = *(const float4*)&vs[sub + kk][part * 16 + c * 4];
                    vr[c * 4 + 0] = v.x; vr[c * 4 + 1] = v.y;
                    vr[c * 4 + 2] = v.z; vr[c * 4 + 3] = v.w;
                }
                #pragma unroll
                for (int r = 0; r < 2; r++) {
                    float p = s[r][kk];
                    #pragma unroll
                    for (int j = 0; j < 16; j++) of[r][j] += p * vr[j];
                }
            }
        }
        __syncthreads();
    }

    #pragma unroll
    for (int r = 0; r < 2; r++) {
        int n = chunk * CHUNK + qt * BQ + qg * 2 + r;
        float inv = 1.0f / lrow[r];
        float* op = outp + ((size_t)(b * NSEQ + n)) * DIM + h * HD + part * 16;
        #pragma unroll
        for (int c = 0; c < 4; c++) {
            float4 v;
            v.x = of[r][c * 4 + 0] * inv; v.y = of[r][c * 4 + 1] * inv;
            v.z = of[r][c * 4 + 2] * inv; v.w = of[r][c * 4 + 3] * inv;
            *(float4*)(op + c * 4) = v;
        }
    }
}

// ------------------------------------------------------------------- launch
extern "C" void kernel_launch(void* const* d_in, const int* in_sizes, int n_in,
                              void* d_out, int out_size)
{
    const float* x       = (const float*)d_in[0];
    const float* Wqkv    = (const float*)d_in[1];
    const float* Aqkv    = (const float*)d_in[2];
    const float* Bqkv    = (const float*)d_in[3];
    const float* Wproj   = (const float*)d_in[4];
    const float* Aproj   = (const float*)d_in[5];
    const float* Bproj   = (const float*)d_in[6];
    const int*   experts = (const int*)d_in[7];
    float*       out     = (float*)d_out;

    // expert_indices is int64 in the reference. If the harness delivers it as
    // raw int64 storage, in_sizes[7] counts 2 int32 words per logical element
    // (or reports 4 elements of int64 -> stride 2 over int32 words). Detect:
    //   in_sizes[7] == NCHUNKS      -> int32 elements, stride 1
    //   in_sizes[7] == 2 * NCHUNKS  -> int64 viewed as int32 words, stride 2
    // Values are small non-negative, so the little-endian low word is the value.
    int estride = (in_sizes[7] >= 2 * NCHUNKS) ? 2 : 1;

    float *qkv_p, *h_p, *o_p, *h2_p;
    cudaGetSymbolAddress((void**)&qkv_p, g_qkv);
    cudaGetSymbolAddress((void**)&h_p,   g_h);
    cudaGetSymbolAddress((void**)&o_p,   g_o);
    cudaGetSymbolAddress((void**)&h2_p,  g_h2);

    // 1) H = x @ Aqkv[e]^T
    lora_h_kernel<<<TOKENS / 64, 256>>>(x, Aqkv, h_p, experts, estride);

    // 2) QKV = x @ Wqkv^T + LSCALE * H @ Bqkv[e]^T   (Bqkv[e] viewed as [2304,64])
    {
        dim3 grid(QKV_DIM / 128, TOKENS / 128);
        gemm_fused128<<<grid, 256>>>(x, Wqkv, h_p, Bqkv, qkv_p, QKV_DIM, experts, estride);
    }

    // 3) chunked block-causal attention
    {
        dim3 grid(CHUNK / BQ, BB * HEADS, NCHUNKS);
        attn_kernel<<<grid, 256>>>(qkv_p, o_p);
    }

    // 4) H2 = o @ Aproj[e]^T
    lora_h_kernel<<<TOKENS / 64, 256>>>(o_p, Aproj, h2_p, experts, estride);

    // 5) out = o @ Wproj^T + LSCALE * H2 @ Bproj[e]^T
    {
        dim3 grid(DIM / 128, TOKENS / 128);
        gemm_fused128<<<grid, 256>>>(o_p, Wproj, h2_p, Bproj, out, DIM, experts, estride);
    }
}

// round 4
// speedup vs baseline: 1.8790x; 1.8790x over previous
#include <cuda_runtime.h>
#include <cstddef>

#define DIM     768
#define HEADS   12
#define HD      64
#define RR      64
#define BB      2
#define NSEQ    4096
#define CHUNK   1024
#define NCHUNKS 4
#define TOKENS  (BB*NSEQ)     // 8192
#define QKV_DIM (3*DIM)       // 2304
#define LSCALE  2.0f          // 128 / 64
#define ATT_SCALE 0.125f      // 64^-0.5
#define LOG2E   1.4426950408889634f

// ------------------------------------------------------------------ scratch
__device__ float g_qkv[(size_t)TOKENS * QKV_DIM];  // 75.5 MB: q|k|v per token
__device__ float g_h  [(size_t)TOKENS * RR];       // x @ Aqkv[e]^T
__device__ float g_o  [(size_t)TOKENS * DIM];      // attention output
__device__ float g_h2 [(size_t)TOKENS * RR];       // o @ Aproj[e]^T

__device__ __forceinline__ float ex2f(float x) {
    float y; asm("ex2.approx.f32 %0, %1;" : "=f"(y) : "f"(x)); return y;
}

// expert index helper: estride=1 -> int32 array, estride=2 -> int64 viewed
// as int32 words (little-endian low word carries the value).
__device__ __forceinline__ int expert_of(const int* ex, int chunk, int estride) {
    return ex[chunk * estride];
}

// ------------------------------------------------------ small LoRA-A GEMM
// C[M x 64] = A[M x 768] @ W_e[64 x 768]^T. Tile M=32 -> 256 blocks (fills chip).
__global__ void __launch_bounds__(256) lora_h_kernel(
    const float* __restrict__ A, const float* __restrict__ Wbase,
    float* __restrict__ C, const int* __restrict__ experts, int estride)
{
    const int m0 = blockIdx.x * 32;
    const int e  = expert_of(experts, (m0 % NSEQ) / CHUNK, estride);
    const float* W = Wbase + (size_t)e * RR * DIM;

    __shared__ float As[16][33];
    __shared__ float Bs[16][65];

    const int tid = threadIdx.x;
    const int tx  = tid & 15;   // 4 output cols each
    const int ty  = tid >> 4;   // 2 output rows each

    float acc[2][4] = {};

    for (int k0 = 0; k0 < DIM; k0 += 16) {
        #pragma unroll
        for (int l = 0; l < 2; l++) {             // A: 32 x 16 = 512
            int idx = tid + l * 256;
            int r = idx >> 4, kk = idx & 15;
            As[kk][r] = A[(size_t)(m0 + r) * DIM + k0 + kk];
        }
        #pragma unroll
        for (int l = 0; l < 4; l++) {             // W: 64 x 16 = 1024
            int idx = tid + l * 256;
            int r = idx >> 4, kk = idx & 15;
            Bs[kk][r] = W[(size_t)r * DIM + k0 + kk];
        }
        __syncthreads();
        #pragma unroll
        for (int kk = 0; kk < 16; kk++) {
            float a0 = As[kk][ty * 2 + 0];
            float a1 = As[kk][ty * 2 + 1];
            float b[4];
            #pragma unroll
            for (int j = 0; j < 4; j++) b[j] = Bs[kk][tx * 4 + j];
            #pragma unroll
            for (int j = 0; j < 4; j++) {
                acc[0][j] += a0 * b[j];
                acc[1][j] += a1 * b[j];
            }
        }
        __syncthreads();
    }
    #pragma unroll
    for (int i = 0; i < 2; i++)
        #pragma unroll
        for (int j = 0; j < 4; j++)
            C[(size_t)(m0 + ty * 2 + i) * RR + tx * 4 + j] = acc[i][j];
}

// ---------------------------------------------- fused main GEMM (+LoRA B)
// C[M x N] = A[M x 768] @ W[N x 768]^T + LSCALE * Hm[M x 64] @ Bl_e[N x 64]^T
// Tile 128x128, 256 threads, 8x8 per thread.
__global__ void __launch_bounds__(256, 2) gemm_fused128(
    const float* __restrict__ A,  const float* __restrict__ W,
    const float* __restrict__ Hm, const float* __restrict__ Blora,
    float* __restrict__ C, int N, const int* __restrict__ experts, int estride)
{
    const int m0 = blockIdx.y * 128;
    const int n0 = blockIdx.x * 128;
    const int e  = expert_of(experts, (m0 % NSEQ) / CHUNK, estride);

    __shared__ float As[16][132];
    __shared__ float Bs[16][132];

    const int tid = threadIdx.x;
    const int tx  = tid & 15;
    const int ty  = tid >> 4;

    float acc[8][8] = {};

    // main K = 768
    for (int k0 = 0; k0 < DIM; k0 += 16) {
        #pragma unroll
        for (int l = 0; l < 2; l++) {
            int idx = tid + l * 256;          // 0..511 float4 slots
            int row = idx >> 2;
            int k4  = (idx & 3) * 4;
            float4 av = *(const float4*)(A + (size_t)(m0 + row) * DIM + k0 + k4);
            float4 bv = *(const float4*)(W + (size_t)(n0 + row) * DIM + k0 + k4);
            As[k4 + 0][row] = av.x; As[k4 + 1][row] = av.y;
            As[k4 + 2][row] = av.z; As[k4 + 3][row] = av.w;
            Bs[k4 + 0][row] = bv.x; Bs[k4 + 1][row] = bv.y;
            Bs[k4 + 2][row] = bv.z; Bs[k4 + 3][row] = bv.w;
        }
        __syncthreads();
        #pragma unroll
        for (int kk = 0; kk < 16; kk++) {
            float a[8], b[8];
            #pragma unroll
            for (int i = 0; i < 8; i++) a[i] = As[kk][ty * 8 + i];
            #pragma unroll
            for (int j = 0; j < 8; j++) b[j] = Bs[kk][tx * 8 + j];
            #pragma unroll
            for (int i = 0; i < 8; i++)
                #pragma unroll
                for (int j = 0; j < 8; j++) acc[i][j] += a[i] * b[j];
        }
        __syncthreads();
    }

    // LoRA K = 64 (A-side values pre-scaled by LSCALE)
    {
        const float* Bw = Blora + (size_t)e * N * RR;
        for (int k0 = 0; k0 < RR; k0 += 16) {
            #pragma unroll
            for (int l = 0; l < 2; l++) {
                int idx = tid + l * 256;
                int row = idx >> 2;
                int k4  = (idx & 3) * 4;
                float4 av = *(const float4*)(Hm + (size_t)(m0 + row) * RR + k0 + k4);
                float4 bv = *(const float4*)(Bw + (size_t)(n0 + row) * RR + k0 + k4);
                As[k4 + 0][row] = av.x * LSCALE; As[k4 + 1][row] = av.y * LSCALE;
                As[k4 + 2][row] = av.z * LSCALE; As[k4 + 3][row] = av.w * LSCALE;
                Bs[k4 + 0][row] = bv.x; Bs[k4 + 1][row] = bv.y;
                Bs[k4 + 2][row] = bv.z; Bs[k4 + 3][row] = bv.w;
            }
            __syncthreads();
            #pragma unroll
            for (int kk = 0; kk < 16; kk++) {
                float a[8], b[8];
                #pragma unroll
                for (int i = 0; i < 8; i++) a[i] = As[kk][ty * 8 + i];
                #pragma unroll
                for (int j = 0; j < 8; j++) b[j] = Bs[kk][tx * 8 + j];
                #pragma unroll
                for (int i = 0; i < 8; i++)
                    #pragma unroll
                    for (int j = 0; j < 8; j++) acc[i][j] += a[i] * b[j];
            }
            __syncthreads();
        }
    }

    #pragma unroll
    for (int i = 0; i < 8; i++) {
        size_t row = (size_t)(m0 + ty * 8 + i);
        #pragma unroll
        for (int j4 = 0; j4 < 2; j4++) {
            float4 v;
            v.x = acc[i][j4 * 4 + 0]; v.y = acc[i][j4 * 4 + 1];
            v.z = acc[i][j4 * 4 + 2]; v.w = acc[i][j4 * 4 + 3];
            *(float4*)(C + row * N + n0 + tx * 8 + j4 * 4) = v;
        }
    }
}

// -------------------------------------------------------- flash attention v2
// grid: (q-tiles = 8, B*HEADS = 24, NCHUNKS = 4, heavy chunk mapped first)
// 256 threads: tid&1 selects a 32-dim slice, tid>>1 is the query row (128 rows).
// 32-key smem tiles; online softmax per 16-key subtile in exp2 domain; one
// shfl_xor(1) per score to reduce the 2 d-slices.
#define BQ 128
#define BK 32

__global__ void __launch_bounds__(256, 2) attn_kernel(
    const float* __restrict__ qkv, float* __restrict__ outp)
{
    __shared__ float ks[BK][HD];
    __shared__ float vs[BK][HD];

    const int qt    = blockIdx.x;               // 0..7
    const int b     = blockIdx.y / HEADS;
    const int h     = blockIdx.y % HEADS;
    const int chunk = (NCHUNKS - 1) - blockIdx.z;  // heavy chunks launch first
    const int tid   = threadIdx.x;
    const int part  = tid & 1;                  // 32-dim slice
    const int row   = tid >> 1;                 // 0..127
    const int kl    = (chunk + 1) * CHUNK;      // visible keys

    const int n = chunk * CHUNK + qt * BQ + row;

    float qf[32];
    {
        const float* qp = qkv + ((size_t)(b * NSEQ + n)) * QKV_DIM + h * HD + part * 32;
        const float qs = ATT_SCALE * LOG2E;     // fold log2(e) into q for exp2 softmax
        #pragma unroll
        for (int c = 0; c < 8; c++) {
            float4 v = *(const float4*)(qp + c * 4);
            qf[c * 4 + 0] = v.x * qs; qf[c * 4 + 1] = v.y * qs;
            qf[c * 4 + 2] = v.z * qs; qf[c * 4 + 3] = v.w * qs;
        }
    }

    float of[32] = {};
    float m = -1e30f, l = 0.f;

    for (int kt = 0; kt < kl; kt += BK) {
        #pragma unroll
        for (int l4 = 0; l4 < 2; l4++) {
            int idx = tid + l4 * 256;           // 0..511 float4 slots
            int r   = idx >> 4;                 // key row 0..31
            int c4  = (idx & 15) * 4;
            size_t base = ((size_t)(b * NSEQ + kt + r)) * QKV_DIM + h * HD + c4;
            *(float4*)&ks[r][c4] = *(const float4*)(qkv + base + DIM);
            *(float4*)&vs[r][c4] = *(const float4*)(qkv + base + 2 * DIM);
        }
        __syncthreads();

        #pragma unroll
        for (int sub = 0; sub < BK; sub += 16) {
            float s[16];
            #pragma unroll
            for (int kk = 0; kk < 16; kk++) s[kk] = 0.f;

            // Q . K over this thread's 32-dim slice, 16 independent chains
            #pragma unroll
            for (int c = 0; c < 8; c++) {
                float a0 = qf[c * 4 + 0], a1 = qf[c * 4 + 1];
                float a2 = qf[c * 4 + 2], a3 = qf[c * 4 + 3];
                #pragma unroll
                for (int kk = 0; kk < 16; kk++) {
                    float4 kv = *(const float4*)&ks[sub + kk][part * 32 + c * 4];
                    s[kk] += a0 * kv.x + a1 * kv.y + a2 * kv.z + a3 * kv.w;
                }
            }
            // reduce the two d-slices (lanes differ only in bit 0)
            #pragma unroll
            for (int kk = 0; kk < 16; kk++)
                s[kk] += __shfl_xor_sync(0xffffffffu, s[kk], 1);

            // online softmax (base-2 domain)
            float mt = s[0];
            #pragma unroll
            for (int kk = 1; kk < 16; kk++) mt = fmaxf(mt, s[kk]);
            float mn   = fmaxf(m, mt);
            float corr = ex2f(m - mn);
            m = mn;
            l *= corr;
            #pragma unroll
            for (int j = 0; j < 32; j++) of[j] *= corr;
            #pragma unroll
            for (int kk = 0; kk < 16; kk++) {
                s[kk] = ex2f(s[kk] - mn);
                l += s[kk];
            }

            // P @ V
            #pragma unroll
            for (int c = 0; c < 8; c++) {
                #pragma unroll
                for (int kk = 0; kk < 16; kk++) {
                    float4 vv = *(const float4*)&vs[sub + kk][part * 32 + c * 4];
                    of[c * 4 + 0] += s[kk] * vv.x;
                    of[c * 4 + 1] += s[kk] * vv.y;
                    of[c * 4 + 2] += s[kk] * vv.z;
                    of[c * 4 + 3] += s[kk] * vv.w;
                }
            }
        }
        __syncthreads();
    }

    const float inv = 1.0f / l;
    float* op = outp + ((size_t)(b * NSEQ + n)) * DIM + h * HD + part * 32;
    #pragma unroll
    for (int c = 0; c < 8; c++) {
        float4 v;
        v.x = of[c * 4 + 0] * inv; v.y = of[c * 4 + 1] * inv;
        v.z = of[c * 4 + 2] * inv; v.w = of[c * 4 + 3] * inv;
        *(float4*)(op + c * 4) = v;
    }
}

// ------------------------------------------------------------------- launch
extern "C" void kernel_launch(void* const* d_in, const int* in_sizes, int n_in,
                              void* d_out, int out_size)
{
    const float* x       = (const float*)d_in[0];
    const float* Wqkv    = (const float*)d_in[1];
    const float* Aqkv    = (const float*)d_in[2];
    const float* Bqkv    = (const float*)d_in[3];
    const float* Wproj   = (const float*)d_in[4];
    const float* Aproj   = (const float*)d_in[5];
    const float* Bproj   = (const float*)d_in[6];
    const int*   experts = (const int*)d_in[7];
    float*       out     = (float*)d_out;

    // expert_indices is int64 in the reference; harness may deliver it as raw
    // int64 storage (2 int32 words per element, little-endian low word first).
    int estride = (in_sizes[7] >= 2 * NCHUNKS) ? 2 : 1;

    float *qkv_p, *h_p, *o_p, *h2_p;
    cudaGetSymbolAddress((void**)&qkv_p, g_qkv);
    cudaGetSymbolAddress((void**)&h_p,   g_h);
    cudaGetSymbolAddress((void**)&o_p,   g_o);
    cudaGetSymbolAddress((void**)&h2_p,  g_h2);

    // 1) H = x @ Aqkv[e]^T
    lora_h_kernel<<<TOKENS / 32, 256>>>(x, Aqkv, h_p, experts, estride);

    // 2) QKV = x @ Wqkv^T + LSCALE * H @ Bqkv[e]^T   (Bqkv[e] viewed as [2304,64])
    {
        dim3 grid(QKV_DIM / 128, TOKENS / 128);
        gemm_fused128<<<grid, 256>>>(x, Wqkv, h_p, Bqkv, qkv_p, QKV_DIM, experts, estride);
    }

    // 3) chunked block-causal attention
    {
        dim3 grid(CHUNK / BQ, BB * HEADS, NCHUNKS);
        attn_kernel<<<grid, 256>>>(qkv_p, o_p);
    }

    // 4) H2 = o @ Aproj[e]^T
    lora_h_kernel<<<TOKENS / 32, 256>>>(o_p, Aproj, h2_p, experts, estride);

    // 5) out = o @ Wproj^T + LSCALE * H2 @ Bproj[e]^T
    {
        dim3 grid(DIM / 128, TOKENS / 128);
        gemm_fused128<<<grid, 256>>>(o_p, Wproj, h2_p, Bproj, out, DIM, experts, estride);
    }
}

// round 6
// speedup vs baseline: 2.1235x; 1.1301x over previous
#include <cuda_runtime.h>
#include <cuda_bf16.h>
#include <cstdint>
#include <cstddef>

#define DIM     768
#define HEADS   12
#define HD      64
#define RR      64
#define BB      2
#define NSEQ    4096
#define CHUNK   1024
#define NCHUNKS 4
#define TOKENS  (BB*NSEQ)     // 8192
#define QKV_DIM (3*DIM)       // 2304
#define NEXP    8
#define LSCALE  2.0f          // 128 / 64
#define ATT_SCALE 0.125f      // 64^-0.5
#define LOG2E   1.4426950408889634f

// ------------------------------------------------------------------ scratch
__device__ float g_qkv[(size_t)TOKENS * QKV_DIM];   // fp32 q|k|v per token
__device__ float g_o  [(size_t)TOKENS * DIM];       // attention output fp32

// bf16 hi/lo split buffers
__device__ __nv_bfloat16 g_xh [(size_t)TOKENS * DIM],   g_xl [(size_t)TOKENS * DIM];
__device__ __nv_bfloat16 g_oh [(size_t)TOKENS * DIM],   g_ol [(size_t)TOKENS * DIM];
__device__ __nv_bfloat16 g_wqh[(size_t)QKV_DIM * DIM],  g_wql[(size_t)QKV_DIM * DIM];
__device__ __nv_bfloat16 g_wph[(size_t)DIM * DIM],      g_wpl[(size_t)DIM * DIM];
__device__ __nv_bfloat16 g_bqh[(size_t)NEXP * QKV_DIM * RR], g_bql[(size_t)NEXP * QKV_DIM * RR];
__device__ __nv_bfloat16 g_bph[(size_t)NEXP * DIM * RR],     g_bpl[(size_t)NEXP * DIM * RR];
__device__ __nv_bfloat16 g_hh [(size_t)TOKENS * RR],    g_hl [(size_t)TOKENS * RR];

// ------------------------------------------------------------------ helpers
__device__ __forceinline__ float ex2f(float x) {
    float y; asm("ex2.approx.f32 %0, %1;" : "=f"(y) : "f"(x)); return y;
}
__device__ __forceinline__ uint32_t s2u(const void* p) {
    uint32_t a;
    asm("{ .reg .u64 t; cvta.to.shared.u64 t, %1; cvt.u32.u64 %0, t; }" : "=r"(a) : "l"(p));
    return a;
}
__device__ __forceinline__ void cpa16(uint32_t d, const void* s) {
    asm volatile("cp.async.cg.shared.global [%0], [%1], 16;" :: "r"(d), "l"(s));
}
#define CP_COMMIT() asm volatile("cp.async.commit_group;" ::: "memory")
#define CP_WAIT1()  asm volatile("cp.async.wait_group 1;" ::: "memory")
#define CP_WAIT0()  asm volatile("cp.async.wait_group 0;" ::: "memory")

__device__ __forceinline__ void mma_bf16(float* d, const uint32_t* a, const uint32_t* b) {
    asm volatile(
        "mma.sync.aligned.m16n8k16.row.col.f32.bf16.bf16.f32 "
        "{%0,%1,%2,%3}, {%4,%5,%6,%7}, {%8,%9}, {%0,%1,%2,%3};"
        : "+f"(d[0]), "+f"(d[1]), "+f"(d[2]), "+f"(d[3])
        : "r"(a[0]), "r"(a[1]), "r"(a[2]), "r"(a[3]), "r"(b[0]), "r"(b[1]));
}

__device__ __forceinline__ int expert_of(const int* ex, int chunk, int estride) {
    return ex[chunk * estride];
}

// ------------------------------------------------------------------ split
// fp32 -> bf16 hi + bf16 lo (lo = v - float(hi)), vectorized by 4.
__global__ void __launch_bounds__(256) split_kernel(
    const float* __restrict__ src, __nv_bfloat16* __restrict__ hi,
    __nv_bfloat16* __restrict__ lo, int n4)
{
    int i = blockIdx.x * blockDim.x + threadIdx.x;
    if (i >= n4) return;
    float4 v = *(const float4*)(src + (size_t)i * 4);
    __nv_bfloat16 h0 = __float2bfloat16(v.x), h1 = __float2bfloat16(v.y);
    __nv_bfloat16 h2 = __float2bfloat16(v.z), h3 = __float2bfloat16(v.w);
    __nv_bfloat16 l0 = __float2bfloat16(v.x - __bfloat162float(h0));
    __nv_bfloat16 l1 = __float2bfloat16(v.y - __bfloat162float(h1));
    __nv_bfloat16 l2 = __float2bfloat16(v.z - __bfloat162float(h2));
    __nv_bfloat16 l3 = __float2bfloat16(v.w - __bfloat162float(h3));
    __nv_bfloat162 a, b;
    a.x = h0; a.y = h1; b.x = h2; b.y = h3;
    *(__nv_bfloat162*)(hi + (size_t)i * 4)     = a;
    *(__nv_bfloat162*)(hi + (size_t)i * 4 + 2) = b;
    a.x = l0; a.y = l1; b.x = l2; b.y = l3;
    *(__nv_bfloat162*)(lo + (size_t)i * 4)     = a;
    *(__nv_bfloat162*)(lo + (size_t)i * 4 + 2) = b;
}

// ------------------------------------------------------ small LoRA-A GEMM
// Hsplit[M x 64] = split(LSCALE * (A[M x 768] @ W_e[64 x 768]^T)). Tile M=32.
__global__ void __launch_bounds__(256) lora_h_kernel(
    const float* __restrict__ A, const float* __restrict__ Wbase,
    __nv_bfloat16* __restrict__ Ch, __nv_bfloat16* __restrict__ Cl,
    const int* __restrict__ experts, int estride)
{
    const int m0 = blockIdx.x * 32;
    const int e  = expert_of(experts, (m0 % NSEQ) / CHUNK, estride);
    const float* W = Wbase + (size_t)e * RR * DIM;

    __shared__ float As[16][33];
    __shared__ float Bs[16][65];

    const int tid = threadIdx.x;
    const int tx  = tid & 15;
    const int ty  = tid >> 4;

    float acc[2][4] = {};

    for (int k0 = 0; k0 < DIM; k0 += 16) {
        #pragma unroll
        for (int l = 0; l < 2; l++) {
            int idx = tid + l * 256;
            int r = idx >> 4, kk = idx & 15;
            As[kk][r] = A[(size_t)(m0 + r) * DIM + k0 + kk];
        }
        #pragma unroll
        for (int l = 0; l < 4; l++) {
            int idx = tid + l * 256;
            int r = idx >> 4, kk = idx & 15;
            Bs[kk][r] = W[(size_t)r * DIM + k0 + kk];
        }
        __syncthreads();
        #pragma unroll
        for (int kk = 0; kk < 16; kk++) {
            float a0 = As[kk][ty * 2 + 0];
            float a1 = As[kk][ty * 2 + 1];
            float b[4];
            #pragma unroll
            for (int j = 0; j < 4; j++) b[j] = Bs[kk][tx * 4 + j];
            #pragma unroll
            for (int j = 0; j < 4; j++) {
                acc[0][j] += a0 * b[j];
                acc[1][j] += a1 * b[j];
            }
        }
        __syncthreads();
    }
    #pragma unroll
    for (int i = 0; i < 2; i++)
        #pragma unroll
        for (int j = 0; j < 4; j++) {
            float v = acc[i][j] * LSCALE;
            __nv_bfloat16 h = __float2bfloat16(v);
            size_t idx = (size_t)(m0 + ty * 2 + i) * RR + tx * 4 + j;
            Ch[idx] = h;
            Cl[idx] = __float2bfloat16(v - __bfloat162float(h));
        }
}

// ------------------------------------------- mma.sync bf16x3 fused GEMM
// C[M x N] = A @ W^T + H @ Bl_e^T (H pre-scaled by LSCALE); operands bf16
// hi/lo; 3 HMMA passes (hh, hl, lh) with fp32 register accumulators.
// Block 128x128, 8 warps (4m x 2n), warp tile 32x64 of m16n8k16.
// K streamed in 32-chunks via 2-stage cp.async pipeline.
#define KCH      32
#define RPADB    80                  // smem row stride bytes (32 bf16 + 8 pad)
#define RPADW    20                  // in 32-bit words
#define ARRB     (128*RPADB)         // 10240 bytes per operand array
#define STAGEB   (4*ARRB)            // Ah | Al | Bh | Bl
#define NCH_MAIN (DIM/KCH)           // 24
#define NCH_TOT  (NCH_MAIN + 2)      // + 2 lora chunks (K=64)
#define MMG_SMEM (2*STAGEB)          // 81920

extern __shared__ char dynsmem[];

__global__ void __launch_bounds__(256, 1) mma_gemm(
    const __nv_bfloat16* __restrict__ Ah, const __nv_bfloat16* __restrict__ Al,
    const __nv_bfloat16* __restrict__ Wh, const __nv_bfloat16* __restrict__ Wl,
    const __nv_bfloat16* __restrict__ Hh, const __nv_bfloat16* __restrict__ Hl,
    const __nv_bfloat16* __restrict__ Blh, const __nv_bfloat16* __restrict__ Bll,
    float* __restrict__ C, int N, const int* __restrict__ experts, int estride)
{
    const int tid = threadIdx.x;
    const int lid = tid & 31;
    const int wid = tid >> 5;
    const int wm  = wid & 3;          // 4 m-warps * 32 rows
    const int wn  = wid >> 2;         // 2 n-warps * 64 cols
    const int g   = lid >> 2;         // octet row/col
    const int q   = lid & 3;
    const int m0  = blockIdx.y * 128;
    const int n0  = blockIdx.x * 128;
    const int e   = expert_of(experts, (m0 % NSEQ) / CHUNK, estride);

    const __nv_bfloat16* beh = Blh + (size_t)e * N * RR;
    const __nv_bfloat16* bel = Bll + (size_t)e * N * RR;

    const uint32_t smem_u = s2u(dynsmem);

    float acc[2][8][4] = {};

    // ---- stage loader: 2 x 16B per array per thread (128 rows x 64B)
    auto issue_load = [&](int c, int s) {
        const __nv_bfloat16 *sa_h, *sa_l, *sb_h, *sb_l;
        int k0, rs;
        if (c < NCH_MAIN) { sa_h = Ah; sa_l = Al; sb_h = Wh;  sb_l = Wl;
                            k0 = c * KCH; rs = DIM; }
        else              { sa_h = Hh; sa_l = Hl; sb_h = beh; sb_l = bel;
                            k0 = (c - NCH_MAIN) * KCH; rs = RR; }
        uint32_t sb = smem_u + s * STAGEB;
        #pragma unroll
        for (int i = 0; i < 2; i++) {
            int idx = tid + i * 256;          // 0..511
            int r   = idx >> 2;               // row 0..127
            int cc  = idx & 3;                // 16B chunk in row
            uint32_t doff = (uint32_t)(r * RPADB + cc * 16);
            size_t  aoff  = (size_t)(m0 + r) * rs + k0 + cc * 8;
            size_t  boff  = (size_t)(n0 + r) * rs + k0 + cc * 8;
            cpa16(sb + 0 * ARRB + doff, sa_h + aoff);
            cpa16(sb + 1 * ARRB + doff, sa_l + aoff);
            cpa16(sb + 2 * ARRB + doff, sb_h + boff);
            cpa16(sb + 3 * ARRB + doff, sb_l + boff);
        }
    };

    issue_load(0, 0);
    CP_COMMIT();

    for (int c = 0; c < NCH_TOT; c++) {
        const int s = c & 1;
        if (c + 1 < NCH_TOT) { issue_load(c + 1, s ^ 1); CP_COMMIT(); CP_WAIT1(); }
        else                 { CP_WAIT0(); }
        __syncthreads();

        const uint32_t* pAh = (const uint32_t*)(dynsmem + s * STAGEB + 0 * ARRB);
        const uint32_t* pAl = (const uint32_t*)(dynsmem + s * STAGEB + 1 * ARRB);
        const uint32_t* pBh = (const uint32_t*)(dynsmem + s * STAGEB + 2 * ARRB);
        const uint32_t* pBl = (const uint32_t*)(dynsmem + s * STAGEB + 3 * ARRB);

        #pragma unroll
        for (int k16 = 0; k16 < KCH / 16; k16++) {
            const int kw = k16 * 8 + q;
            uint32_t ah[2][4], al[2][4], bh[8][2], bl[8][2];
            #pragma unroll
            for (int mt = 0; mt < 2; mt++) {
                int r = wm * 32 + mt * 16 + g;
                ah[mt][0] = pAh[r * RPADW + kw];
                ah[mt][1] = pAh[(r + 8) * RPADW + kw];
                ah[mt][2] = pAh[r * RPADW + kw + 4];
                ah[mt][3] = pAh[(r + 8) * RPADW + kw + 4];
                al[mt][0] = pAl[r * RPADW + kw];
                al[mt][1] = pAl[(r + 8) * RPADW + kw];
                al[mt][2] = pAl[r * RPADW + kw + 4];
                al[mt][3] = pAl[(r + 8) * RPADW + kw + 4];
            }
            #pragma unroll
            for (int nt = 0; nt < 8; nt++) {
                int r = wn * 64 + nt * 8 + g;
                bh[nt][0] = pBh[r * RPADW + kw];
                bh[nt][1] = pBh[r * RPADW + kw + 4];
                bl[nt][0] = pBl[r * RPADW + kw];
                bl[nt][1] = pBl[r * RPADW + kw + 4];
            }
            #pragma unroll
            for (int mt = 0; mt < 2; mt++)
                #pragma unroll
                for (int nt = 0; nt < 8; nt++)
                    mma_bf16(acc[mt][nt], ah[mt], bh[nt]);   // hi*hi
            #pragma unroll
            for (int mt = 0; mt < 2; mt++)
                #pragma unroll
                for (int nt = 0; nt < 8; nt++)
                    mma_bf16(acc[mt][nt], ah[mt], bl[nt]);   // hi*lo
            #pragma unroll
            for (int mt = 0; mt < 2; mt++)
                #pragma unroll
                for (int nt = 0; nt < 8; nt++)
                    mma_bf16(acc[mt][nt], al[mt], bh[nt]);   // lo*hi
        }
        __syncthreads();
    }

    // ---- epilogue
    #pragma unroll
    for (int mt = 0; mt < 2; mt++) {
        int row = m0 + wm * 32 + mt * 16 + g;
        #pragma unroll
        for (int nt = 0; nt < 8; nt++) {
            int col = n0 + wn * 64 + nt * 8 + q * 2;
            *(float2*)(C + (size_t)row * N + col) =
                make_float2(acc[mt][nt][0], acc[mt][nt][1]);
            *(float2*)(C + (size_t)(row + 8) * N + col) =
                make_float2(acc[mt][nt][2], acc[mt][nt][3]);
        }
    }
}

// -------------------------------------------------------- flash attention
#define BQ 128
#define BK 32

__global__ void __launch_bounds__(256, 2) attn_kernel(
    const float* __restrict__ qkv, float* __restrict__ outp)
{
    __shared__ float ks[BK][HD];
    __shared__ float vs[BK][HD];

    const int qt    = blockIdx.x;
    const int b     = blockIdx.y / HEADS;
    const int h     = blockIdx.y % HEADS;
    const int chunk = (NCHUNKS - 1) - blockIdx.z;  // heavy chunks launch first
    const int tid   = threadIdx.x;
    const int part  = tid & 1;
    const int row   = tid >> 1;
    const int kl    = (chunk + 1) * CHUNK;

    const int n = chunk * CHUNK + qt * BQ + row;

    float qf[32];
    {
        const float* qp = qkv + ((size_t)(b * NSEQ + n)) * QKV_DIM + h * HD + part * 32;
        const float qs = ATT_SCALE * LOG2E;
        #pragma unroll
        for (int c = 0; c < 8; c++) {
            float4 v = *(const float4*)(qp + c * 4);
            qf[c * 4 + 0] = v.x * qs; qf[c * 4 + 1] = v.y * qs;
            qf[c * 4 + 2] = v.z * qs; qf[c * 4 + 3] = v.w * qs;
        }
    }

    float of[32] = {};
    float m = -1e30f, l = 0.f;

    for (int kt = 0; kt < kl; kt += BK) {
        #pragma unroll
        for (int l4 = 0; l4 < 2; l4++) {
            int idx = tid + l4 * 256;
            int r   = idx >> 4;
            int c4  = (idx & 15) * 4;
            size_t base = ((size_t)(b * NSEQ + kt + r)) * QKV_DIM + h * HD + c4;
            *(float4*)&ks[r][c4] = *(const float4*)(qkv + base + DIM);
            *(float4*)&vs[r][c4] = *(const float4*)(qkv + base + 2 * DIM);
        }
        __syncthreads();

        #pragma unroll
        for (int sub = 0; sub < BK; sub += 16) {
            float s[16];
            #pragma unroll
            for (int kk = 0; kk < 16; kk++) s[kk] = 0.f;

            #pragma unroll
            for (int c = 0; c < 8; c++) {
                float a0 = qf[c * 4 + 0], a1 = qf[c * 4 + 1];
                float a2 = qf[c * 4 + 2], a3 = qf[c * 4 + 3];
                #pragma unroll
                for (int kk = 0; kk < 16; kk++) {
                    float4 kv = *(const float4*)&ks[sub + kk][part * 32 + c * 4];
                    s[kk] += a0 * kv.x + a1 * kv.y + a2 * kv.z + a3 * kv.w;
                }
            }
            #pragma unroll
            for (int kk = 0; kk < 16; kk++)
                s[kk] += __shfl_xor_sync(0xffffffffu, s[kk], 1);

            float mt = s[0];
            #pragma unroll
            for (int kk = 1; kk < 16; kk++) mt = fmaxf(mt, s[kk]);
            float mn   = fmaxf(m, mt);
            float corr = ex2f(m - mn);
            m = mn;
            l *= corr;
            #pragma unroll
            for (int j = 0; j < 32; j++) of[j] *= corr;
            #pragma unroll
            for (int kk = 0; kk < 16; kk++) {
                s[kk] = ex2f(s[kk] - mn);
                l += s[kk];
            }

            #pragma unroll
            for (int c = 0; c < 8; c++) {
                #pragma unroll
                for (int kk = 0; kk < 16; kk++) {
                    float4 vv = *(const float4*)&vs[sub + kk][part * 32 + c * 4];
                    of[c * 4 + 0] += s[kk] * vv.x;
                    of[c * 4 + 1] += s[kk] * vv.y;
                    of[c * 4 + 2] += s[kk] * vv.z;
                    of[c * 4 + 3] += s[kk] * vv.w;
                }
            }
        }
        __syncthreads();
    }

    const float inv = 1.0f / l;
    float* op = outp + ((size_t)(b * NSEQ + n)) * DIM + h * HD + part * 32;
    #pragma unroll
    for (int c = 0; c < 8; c++) {
        float4 v;
        v.x = of[c * 4 + 0] * inv; v.y = of[c * 4 + 1] * inv;
        v.z = of[c * 4 + 2] * inv; v.w = of[c * 4 + 3] * inv;
        *(float4*)(op + c * 4) = v;
    }
}

// ------------------------------------------------------------------- launch
static inline void run_split(const float* src, __nv_bfloat16* hi, __nv_bfloat16* lo, size_t n) {
    int n4 = (int)(n / 4);
    split_kernel<<<(n4 + 255) / 256, 256>>>(src, hi, lo, n4);
}

extern "C" void kernel_launch(void* const* d_in, const int* in_sizes, int n_in,
                              void* d_out, int out_size)
{
    const float* x       = (const float*)d_in[0];
    const float* Wqkv    = (const float*)d_in[1];
    const float* Aqkv    = (const float*)d_in[2];
    const float* Bqkv    = (const float*)d_in[3];
    const float* Wproj   = (const float*)d_in[4];
    const float* Aproj   = (const float*)d_in[5];
    const float* Bproj   = (const float*)d_in[6];
    const int*   experts = (const int*)d_in[7];
    float*       out     = (float*)d_out;

    int estride = (in_sizes[7] >= 2 * NCHUNKS) ? 2 : 1;

    float *qkv_p, *o_p;
    __nv_bfloat16 *xh, *xl, *oh, *ol, *wqh, *wql, *wph, *wpl;
    __nv_bfloat16 *bqh, *bql, *bph, *bpl, *hh, *hl;
    cudaGetSymbolAddress((void**)&qkv_p, g_qkv);
    cudaGetSymbolAddress((void**)&o_p,   g_o);
    cudaGetSymbolAddress((void**)&xh,  g_xh);  cudaGetSymbolAddress((void**)&xl,  g_xl);
    cudaGetSymbolAddress((void**)&oh,  g_oh);  cudaGetSymbolAddress((void**)&ol,  g_ol);
    cudaGetSymbolAddress((void**)&wqh, g_wqh); cudaGetSymbolAddress((void**)&wql, g_wql);
    cudaGetSymbolAddress((void**)&wph, g_wph); cudaGetSymbolAddress((void**)&wpl, g_wpl);
    cudaGetSymbolAddress((void**)&bqh, g_bqh); cudaGetSymbolAddress((void**)&bql, g_bql);
    cudaGetSymbolAddress((void**)&bph, g_bph); cudaGetSymbolAddress((void**)&bpl, g_bpl);
    cudaGetSymbolAddress((void**)&hh,  g_hh);  cudaGetSymbolAddress((void**)&hl,  g_hl);

    cudaFuncSetAttribute(mma_gemm, cudaFuncAttributeMaxDynamicSharedMemorySize, MMG_SMEM);

    // 0) split fp32 operands into bf16 hi/lo
    run_split(x,     xh,  xl,  (size_t)TOKENS * DIM);
    run_split(Wqkv,  wqh, wql, (size_t)QKV_DIM * DIM);
    run_split(Bqkv,  bqh, bql, (size_t)NEXP * QKV_DIM * RR);
    run_split(Wproj, wph, wpl, (size_t)DIM * DIM);
    run_split(Bproj, bph, bpl, (size_t)NEXP * DIM * RR);

    // 1) H = split(LSCALE * x @ Aqkv[e]^T)
    lora_h_kernel<<<TOKENS / 32, 256>>>(x, Aqkv, hh, hl, experts, estride);

    // 2) QKV = x @ Wqkv^T + H @ Bqkv[e]^T (bf16x3 HMMA)
    {
        dim3 grid(QKV_DIM / 128, TOKENS / 128);
        mma_gemm<<<grid, 256, MMG_SMEM>>>(xh, xl, wqh, wql, hh, hl, bqh, bql,
                                          qkv_p, QKV_DIM, experts, estride);
    }

    // 3) chunked block-causal attention (fp32 SIMT)
    {
        dim3 grid(CHUNK / BQ, BB * HEADS, NCHUNKS);
        attn_kernel<<<grid, 256>>>(qkv_p, o_p);
    }

    // 4) split o; H2 = split(LSCALE * o @ Aproj[e]^T)
    run_split(o_p, oh, ol, (size_t)TOKENS * DIM);
    lora_h_kernel<<<TOKENS / 32, 256>>>(o_p, Aproj, hh, hl, experts, estride);

    // 5) out = o @ Wproj^T + H2 @ Bproj[e]^T (bf16x3 HMMA)
    {
        dim3 grid(DIM / 128, TOKENS / 128);
        mma_gemm<<<grid, 256, MMG_SMEM>>>(oh, ol, wph, wpl, hh, hl, bph, bpl,
                                          out, DIM, experts, estride);
    }
}

// round 7
// speedup vs baseline: 7.3557x; 3.4640x over previous
#include <cuda_runtime.h>
#include <cuda_bf16.h>
#include <cstdint>
#include <cstddef>

#define DIM     768
#define HEADS   12
#define HD      64
#define RR      64
#define BB      2
#define NSEQ    4096
#define CHUNK   1024
#define NCHUNKS 4
#define TOKENS  (BB*NSEQ)     // 8192
#define QKV_DIM (3*DIM)       // 2304
#define NEXP    8
#define LSCALE  2.0f          // 128 / 64
#define ATT_SCALE 0.125f      // 64^-0.5
#define LOG2E   1.4426950408889634f

typedef __nv_bfloat16 bf16;

// ------------------------------------------------------------------ scratch
__device__ float g_qkv[(size_t)TOKENS * QKV_DIM];   // fp32 q|k|v per token
__device__ float g_o  [(size_t)TOKENS * DIM];       // attention output fp32

// bf16 hi/lo split buffers (GEMM operands)
__device__ __align__(16) bf16 g_xh [(size_t)TOKENS * DIM],   g_xl [(size_t)TOKENS * DIM];
__device__ __align__(16) bf16 g_oh [(size_t)TOKENS * DIM],   g_ol [(size_t)TOKENS * DIM];
__device__ __align__(16) bf16 g_wqh[(size_t)QKV_DIM * DIM],  g_wql[(size_t)QKV_DIM * DIM];
__device__ __align__(16) bf16 g_wph[(size_t)DIM * DIM],      g_wpl[(size_t)DIM * DIM];
__device__ __align__(16) bf16 g_bqh[(size_t)NEXP * QKV_DIM * RR], g_bql[(size_t)NEXP * QKV_DIM * RR];
__device__ __align__(16) bf16 g_bph[(size_t)NEXP * DIM * RR],     g_bpl[(size_t)NEXP * DIM * RR];
__device__ __align__(16) bf16 g_hh [(size_t)TOKENS * RR],    g_hl [(size_t)TOKENS * RR];

// attention operands: per (b,h) head-major layouts
__device__ __align__(16) bf16 g_qah[(size_t)BB*HEADS*NSEQ*HD], g_qal[(size_t)BB*HEADS*NSEQ*HD];
__device__ __align__(16) bf16 g_kah[(size_t)BB*HEADS*NSEQ*HD], g_kal[(size_t)BB*HEADS*NSEQ*HD];
__device__ __align__(16) bf16 g_vth[(size_t)BB*HEADS*HD*NSEQ], g_vtl[(size_t)BB*HEADS*HD*NSEQ];

// ------------------------------------------------------------------ helpers
__device__ __forceinline__ float ex2f(float x) {
    float y; asm("ex2.approx.f32 %0, %1;" : "=f"(y) : "f"(x)); return y;
}
__device__ __forceinline__ uint32_t s2u(const void* p) {
    uint32_t a;
    asm("{ .reg .u64 t; cvta.to.shared.u64 t, %1; cvt.u32.u64 %0, t; }" : "=r"(a) : "l"(p));
    return a;
}
__device__ __forceinline__ void cpa16(uint32_t d, const void* s) {
    asm volatile("cp.async.cg.shared.global [%0], [%1], 16;" :: "r"(d), "l"(s));
}
#define CP_COMMIT() asm volatile("cp.async.commit_group;" ::: "memory")
#define CP_WAIT1()  asm volatile("cp.async.wait_group 1;" ::: "memory")
#define CP_WAIT0()  asm volatile("cp.async.wait_group 0;" ::: "memory")

__device__ __forceinline__ void mma_bf16(float* d, const uint32_t* a, const uint32_t* b) {
    asm volatile(
        "mma.sync.aligned.m16n8k16.row.col.f32.bf16.bf16.f32 "
        "{%0,%1,%2,%3}, {%4,%5,%6,%7}, {%8,%9}, {%0,%1,%2,%3};"
        : "+f"(d[0]), "+f"(d[1]), "+f"(d[2]), "+f"(d[3])
        : "r"(a[0]), "r"(a[1]), "r"(a[2]), "r"(a[3]), "r"(b[0]), "r"(b[1]));
}

__device__ __forceinline__ uint32_t pack2(float a, float b) {
    __nv_bfloat162 t = __floats2bfloat162_rn(a, b);
    return *(uint32_t*)&t;
}

__device__ __forceinline__ int expert_of(const int* ex, int chunk, int estride) {
    return ex[chunk * estride];
}

// ------------------------------------------------------------------ split
__global__ void __launch_bounds__(256) split_kernel(
    const float* __restrict__ src, bf16* __restrict__ hi,
    bf16* __restrict__ lo, int n4)
{
    int i = blockIdx.x * blockDim.x + threadIdx.x;
    if (i >= n4) return;
    float4 v = *(const float4*)(src + (size_t)i * 4);
    bf16 h0 = __float2bfloat16(v.x), h1 = __float2bfloat16(v.y);
    bf16 h2 = __float2bfloat16(v.z), h3 = __float2bfloat16(v.w);
    bf16 l0 = __float2bfloat16(v.x - __bfloat162float(h0));
    bf16 l1 = __float2bfloat16(v.y - __bfloat162float(h1));
    bf16 l2 = __float2bfloat16(v.z - __bfloat162float(h2));
    bf16 l3 = __float2bfloat16(v.w - __bfloat162float(h3));
    __nv_bfloat162 a, b;
    a.x = h0; a.y = h1; b.x = h2; b.y = h3;
    *(__nv_bfloat162*)(hi + (size_t)i * 4)     = a;
    *(__nv_bfloat162*)(hi + (size_t)i * 4 + 2) = b;
    a.x = l0; a.y = l1; b.x = l2; b.y = l3;
    *(__nv_bfloat162*)(lo + (size_t)i * 4)     = a;
    *(__nv_bfloat162*)(lo + (size_t)i * 4 + 2) = b;
}

// ------------------------------------------------------ small LoRA-A GEMM
__global__ void __launch_bounds__(256) lora_h_kernel(
    const float* __restrict__ A, const float* __restrict__ Wbase,
    bf16* __restrict__ Ch, bf16* __restrict__ Cl,
    const int* __restrict__ experts, int estride)
{
    const int m0 = blockIdx.x * 32;
    const int e  = expert_of(experts, (m0 % NSEQ) / CHUNK, estride);
    const float* W = Wbase + (size_t)e * RR * DIM;

    __shared__ float As[16][33];
    __shared__ float Bs[16][65];

    const int tid = threadIdx.x;
    const int tx  = tid & 15;
    const int ty  = tid >> 4;

    float acc[2][4] = {};

    for (int k0 = 0; k0 < DIM; k0 += 16) {
        #pragma unroll
        for (int l = 0; l < 2; l++) {
            int idx = tid + l * 256;
            int r = idx >> 4, kk = idx & 15;
            As[kk][r] = A[(size_t)(m0 + r) * DIM + k0 + kk];
        }
        #pragma unroll
        for (int l = 0; l < 4; l++) {
            int idx = tid + l * 256;
            int r = idx >> 4, kk = idx & 15;
            Bs[kk][r] = W[(size_t)r * DIM + k0 + kk];
        }
        __syncthreads();
        #pragma unroll
        for (int kk = 0; kk < 16; kk++) {
            float a0 = As[kk][ty * 2 + 0];
            float a1 = As[kk][ty * 2 + 1];
            float b[4];
            #pragma unroll
            for (int j = 0; j < 4; j++) b[j] = Bs[kk][tx * 4 + j];
            #pragma unroll
            for (int j = 0; j < 4; j++) {
                acc[0][j] += a0 * b[j];
                acc[1][j] += a1 * b[j];
            }
        }
        __syncthreads();
    }
    #pragma unroll
    for (int i = 0; i < 2; i++)
        #pragma unroll
        for (int j = 0; j < 4; j++) {
            float v = acc[i][j] * LSCALE;
            bf16 h = __float2bfloat16(v);
            size_t idx = (size_t)(m0 + ty * 2 + i) * RR + tx * 4 + j;
            Ch[idx] = h;
            Cl[idx] = __float2bfloat16(v - __bfloat162float(h));
        }
}

// ------------------------------------------- mma.sync bf16x3 fused GEMM
#define KCH      32
#define RPADB    80
#define RPADW    20
#define ARRB     (128*RPADB)
#define STAGEB   (4*ARRB)
#define NCH_MAIN (DIM/KCH)           // 24
#define NCH_TOT  (NCH_MAIN + 2)
#define MMG_SMEM (2*STAGEB)          // 81920

extern __shared__ char dynsmem[];

__global__ void __launch_bounds__(256, 1) mma_gemm(
    const bf16* __restrict__ Ah, const bf16* __restrict__ Al,
    const bf16* __restrict__ Wh, const bf16* __restrict__ Wl,
    const bf16* __restrict__ Hh, const bf16* __restrict__ Hl,
    const bf16* __restrict__ Blh, const bf16* __restrict__ Bll,
    float* __restrict__ C, int N, const int* __restrict__ experts, int estride)
{
    const int tid = threadIdx.x;
    const int lid = tid & 31;
    const int wid = tid >> 5;
    const int wm  = wid & 3;
    const int wn  = wid >> 2;
    const int g   = lid >> 2;
    const int q   = lid & 3;
    const int m0  = blockIdx.y * 128;
    const int n0  = blockIdx.x * 128;
    const int e   = expert_of(experts, (m0 % NSEQ) / CHUNK, estride);

    const bf16* beh = Blh + (size_t)e * N * RR;
    const bf16* bel = Bll + (size_t)e * N * RR;

    const uint32_t smem_u = s2u(dynsmem);

    float acc[2][8][4] = {};

    auto issue_load = [&](int c, int s) {
        const bf16 *sa_h, *sa_l, *sb_h, *sb_l;
        int k0, rs;
        if (c < NCH_MAIN) { sa_h = Ah; sa_l = Al; sb_h = Wh;  sb_l = Wl;
                            k0 = c * KCH; rs = DIM; }
        else              { sa_h = Hh; sa_l = Hl; sb_h = beh; sb_l = bel;
                            k0 = (c - NCH_MAIN) * KCH; rs = RR; }
        uint32_t sb = smem_u + s * STAGEB;
        #pragma unroll
        for (int i = 0; i < 2; i++) {
            int idx = tid + i * 256;
            int r   = idx >> 2;
            int cc  = idx & 3;
            uint32_t doff = (uint32_t)(r * RPADB + cc * 16);
            size_t  aoff  = (size_t)(m0 + r) * rs + k0 + cc * 8;
            size_t  boff  = (size_t)(n0 + r) * rs + k0 + cc * 8;
            cpa16(sb + 0 * ARRB + doff, sa_h + aoff);
            cpa16(sb + 1 * ARRB + doff, sa_l + aoff);
            cpa16(sb + 2 * ARRB + doff, sb_h + boff);
            cpa16(sb + 3 * ARRB + doff, sb_l + boff);
        }
    };

    issue_load(0, 0);
    CP_COMMIT();

    for (int c = 0; c < NCH_TOT; c++) {
        const int s = c & 1;
        if (c + 1 < NCH_TOT) { issue_load(c + 1, s ^ 1); CP_COMMIT(); CP_WAIT1(); }
        else                 { CP_WAIT0(); }
        __syncthreads();

        const uint32_t* pAh = (const uint32_t*)(dynsmem + s * STAGEB + 0 * ARRB);
        const uint32_t* pAl = (const uint32_t*)(dynsmem + s * STAGEB + 1 * ARRB);
        const uint32_t* pBh = (const uint32_t*)(dynsmem + s * STAGEB + 2 * ARRB);
        const uint32_t* pBl = (const uint32_t*)(dynsmem + s * STAGEB + 3 * ARRB);

        #pragma unroll
        for (int k16 = 0; k16 < KCH / 16; k16++) {
            const int kw = k16 * 8 + q;
            uint32_t ah[2][4], al[2][4], bh[8][2], bl[8][2];
            #pragma unroll
            for (int mt = 0; mt < 2; mt++) {
                int r = wm * 32 + mt * 16 + g;
                ah[mt][0] = pAh[r * RPADW + kw];
                ah[mt][1] = pAh[(r + 8) * RPADW + kw];
                ah[mt][2] = pAh[r * RPADW + kw + 4];
                ah[mt][3] = pAh[(r + 8) * RPADW + kw + 4];
                al[mt][0] = pAl[r * RPADW + kw];
                al[mt][1] = pAl[(r + 8) * RPADW + kw];
                al[mt][2] = pAl[r * RPADW + kw + 4];
                al[mt][3] = pAl[(r + 8) * RPADW + kw + 4];
            }
            #pragma unroll
            for (int nt = 0; nt < 8; nt++) {
                int r = wn * 64 + nt * 8 + g;
                bh[nt][0] = pBh[r * RPADW + kw];
                bh[nt][1] = pBh[r * RPADW + kw + 4];
                bl[nt][0] = pBl[r * RPADW + kw];
                bl[nt][1] = pBl[r * RPADW + kw + 4];
            }
            #pragma unroll
            for (int mt = 0; mt < 2; mt++)
                #pragma unroll
                for (int nt = 0; nt < 8; nt++)
                    mma_bf16(acc[mt][nt], ah[mt], bh[nt]);
            #pragma unroll
            for (int mt = 0; mt < 2; mt++)
                #pragma unroll
                for (int nt = 0; nt < 8; nt++)
                    mma_bf16(acc[mt][nt], ah[mt], bl[nt]);
            #pragma unroll
            for (int mt = 0; mt < 2; mt++)
                #pragma unroll
                for (int nt = 0; nt < 8; nt++)
                    mma_bf16(acc[mt][nt], al[mt], bh[nt]);
        }
        __syncthreads();
    }

    #pragma unroll
    for (int mt = 0; mt < 2; mt++) {
        int row = m0 + wm * 32 + mt * 16 + g;
        #pragma unroll
        for (int nt = 0; nt < 8; nt++) {
            int col = n0 + wn * 64 + nt * 8 + q * 2;
            *(float2*)(C + (size_t)row * N + col) =
                make_float2(acc[mt][nt][0], acc[mt][nt][1]);
            *(float2*)(C + (size_t)(row + 8) * N + col) =
                make_float2(acc[mt][nt][2], acc[mt][nt][3]);
        }
    }
}

// ------------------------------------------------------------- attn prep
// Q/K: split to bf16 hi/lo in [b,h,n,d] layout; Q pre-scaled by ATT_SCALE*LOG2E.
__global__ void __launch_bounds__(256) prep_qk(
    const float* __restrict__ qkv,
    bf16* __restrict__ Qh, bf16* __restrict__ Ql,
    bf16* __restrict__ Kh, bf16* __restrict__ Kl)
{
    int i4 = blockIdx.x * 256 + threadIdx.x;
    if (i4 >= TOKENS * (DIM / 4)) return;
    int t  = i4 / (DIM / 4);
    int j  = i4 % (DIM / 4);
    int h  = j >> 4;
    int d4 = j & 15;
    int b  = t >> 12, n = t & (NSEQ - 1);

    const float* qp = qkv + (size_t)t * QKV_DIM + h * HD + d4 * 4;
    float4 qv = *(const float4*)qp;
    float4 kv = *(const float4*)(qp + DIM);
    size_t dst = ((size_t)(b * HEADS + h) * NSEQ + n) * HD + d4 * 4;

    const float qs = ATT_SCALE * LOG2E;
    float q0 = qv.x * qs, q1 = qv.y * qs, q2 = qv.z * qs, q3 = qv.w * qs;

    bf16 h0 = __float2bfloat16(q0), h1 = __float2bfloat16(q1);
    bf16 h2 = __float2bfloat16(q2), h3 = __float2bfloat16(q3);
    *(uint32_t*)(Qh + dst)     = pack2(q0, q1);
    *(uint32_t*)(Qh + dst + 2) = pack2(q2, q3);
    *(uint32_t*)(Ql + dst)     = pack2(q0 - __bfloat162float(h0), q1 - __bfloat162float(h1));
    *(uint32_t*)(Ql + dst + 2) = pack2(q2 - __bfloat162float(h2), q3 - __bfloat162float(h3));

    bf16 k0 = __float2bfloat16(kv.x), k1 = __float2bfloat16(kv.y);
    bf16 k2 = __float2bfloat16(kv.z), k3 = __float2bfloat16(kv.w);
    *(uint32_t*)(Kh + dst)     = pack2(kv.x, kv.y);
    *(uint32_t*)(Kh + dst + 2) = pack2(kv.z, kv.w);
    *(uint32_t*)(Kl + dst)     = pack2(kv.x - __bfloat162float(k0), kv.y - __bfloat162float(k1));
    *(uint32_t*)(Kl + dst + 2) = pack2(kv.z - __bfloat162float(k2), kv.w - __bfloat162float(k3));
}

// V: split + transpose to [b,h,d,n] (dim-major) for PV B-fragments.
__global__ void __launch_bounds__(256) prep_vt(
    const float* __restrict__ qkv, bf16* __restrict__ Vth, bf16* __restrict__ Vtl)
{
    __shared__ float vsm[64][65];
    const int n0 = blockIdx.x * 64;
    const int bh = blockIdx.y;
    const int b = bh / HEADS, h = bh % HEADS;
    const int tid = threadIdx.x;

    #pragma unroll
    for (int i = 0; i < 16; i++) {
        int idx = tid + i * 256;
        int r = idx >> 6, d = idx & 63;
        vsm[r][d] = qkv[((size_t)(b * NSEQ + n0 + r)) * QKV_DIM + 2 * DIM + h * HD + d];
    }
    __syncthreads();
    #pragma unroll
    for (int i = 0; i < 16; i++) {
        int idx = tid + i * 256;
        int d = idx >> 6, t = idx & 63;
        float v = vsm[t][d];
        bf16 hh = __float2bfloat16(v);
        size_t o = ((size_t)bh * HD + d) * NSEQ + n0 + t;
        Vth[o] = hh;
        Vtl[o] = __float2bfloat16(v - __bfloat162float(hh));
    }
}

// ------------------------------------------ tensor-core flash attention
// Block: 64 q-rows, 4 warps (16 q-rows each), 64-key tiles.
// Scores: 3x bf16 MMA (qh*kh + qh*kl + ql*kh). P split hi/lo in regs;
// PV: 3x bf16 MMA (ph*vh + ph*vl + pl*vh). All accum fp32. exp2-domain softmax.
#define KSTR 72   // smem row stride in bf16 elems (144B) — conflict-free

__global__ void __launch_bounds__(128) attn_mma(
    const bf16* __restrict__ Qh, const bf16* __restrict__ Ql,
    const bf16* __restrict__ Kh, const bf16* __restrict__ Kl,
    const bf16* __restrict__ Vth, const bf16* __restrict__ Vtl,
    float* __restrict__ outp)
{
    __shared__ __align__(16) bf16 skh[64 * KSTR], skl[64 * KSTR];
    __shared__ __align__(16) bf16 svh[64 * KSTR], svl[64 * KSTR];

    const int qt    = blockIdx.x;
    const int bh    = blockIdx.y;
    const int chunk = (NCHUNKS - 1) - blockIdx.z;   // heavy first
    const int b     = bh / HEADS, h = bh % HEADS;
    const int tid   = threadIdx.x;
    const int w     = tid >> 5, lid = tid & 31;
    const int g     = lid >> 2, q = lid & 3;
    const int klend = (chunk + 1) * CHUNK;

    const bf16* Qbh  = Qh  + (size_t)bh * NSEQ * HD;
    const bf16* Qlbh = Ql  + (size_t)bh * NSEQ * HD;
    const bf16* Kbh  = Kh  + (size_t)bh * NSEQ * HD;
    const bf16* Klbh = Kl  + (size_t)bh * NSEQ * HD;
    const bf16* Vbh  = Vth + (size_t)bh * HD * NSEQ;
    const bf16* Vlbh = Vtl + (size_t)bh * HD * NSEQ;

    const int r0 = chunk * CHUNK + qt * 64 + w * 16 + g;   // this thread's row (and r0+8)

    // Q fragments, resident in registers for the whole block
    uint32_t qhf[4][4], qlf[4][4];
    #pragma unroll
    for (int kk = 0; kk < 4; kk++) {
        size_t base0 = (size_t)r0 * HD + kk * 16 + 2 * q;
        size_t base1 = (size_t)(r0 + 8) * HD + kk * 16 + 2 * q;
        qhf[kk][0] = *(const uint32_t*)(Qbh + base0);
        qhf[kk][1] = *(const uint32_t*)(Qbh + base1);
        qhf[kk][2] = *(const uint32_t*)(Qbh + base0 + 8);
        qhf[kk][3] = *(const uint32_t*)(Qbh + base1 + 8);
        qlf[kk][0] = *(const uint32_t*)(Qlbh + base0);
        qlf[kk][1] = *(const uint32_t*)(Qlbh + base1);
        qlf[kk][2] = *(const uint32_t*)(Qlbh + base0 + 8);
        qlf[kk][3] = *(const uint32_t*)(Qlbh + base1 + 8);
    }

    const uint32_t skh_u = s2u(skh), skl_u = s2u(skl);
    const uint32_t svh_u = s2u(svh), svl_u = s2u(svl);

    float o[8][4] = {};
    float m0 = -1e30f, m1 = -1e30f, l0 = 0.f, l1 = 0.f;

    for (int kt = 0; kt < klend; kt += 64) {
        __syncthreads();
        #pragma unroll
        for (int i = 0; i < 4; i++) {
            int idx = tid + i * 128;
            int r = idx >> 3, c = idx & 7;
            uint32_t doff = (uint32_t)(r * KSTR + c * 8) * 2;
            cpa16(skh_u + doff, Kbh  + (size_t)(kt + r) * HD + c * 8);
            cpa16(skl_u + doff, Klbh + (size_t)(kt + r) * HD + c * 8);
            cpa16(svh_u + doff, Vbh  + (size_t)r * NSEQ + kt + c * 8);
            cpa16(svl_u + doff, Vlbh + (size_t)r * NSEQ + kt + c * 8);
        }
        CP_COMMIT(); CP_WAIT0();
        __syncthreads();

        // ---- scores S = Q.K^T (bf16x3)
        float sc[8][4] = {};
        #pragma unroll
        for (int kk = 0; kk < 4; kk++) {
            #pragma unroll
            for (int nt = 0; nt < 8; nt++) {
                const uint32_t* kr  = (const uint32_t*)(skh + (nt * 8 + g) * KSTR + kk * 16 + 2 * q);
                const uint32_t* klr = (const uint32_t*)(skl + (nt * 8 + g) * KSTR + kk * 16 + 2 * q);
                uint32_t kb[2]  = { kr[0],  kr[4]  };
                uint32_t klb[2] = { klr[0], klr[4] };
                mma_bf16(sc[nt], qhf[kk], kb);
                mma_bf16(sc[nt], qhf[kk], klb);
                mma_bf16(sc[nt], qlf[kk], kb);
            }
        }

        // ---- online softmax (exp2 domain); rows r0 (c0,c1) and r0+8 (c2,c3)
        float mt0 = -1e30f, mt1 = -1e30f;
        #pragma unroll
        for (int nt = 0; nt < 8; nt++) {
            mt0 = fmaxf(mt0, fmaxf(sc[nt][0], sc[nt][1]));
            mt1 = fmaxf(mt1, fmaxf(sc[nt][2], sc[nt][3]));
        }
        mt0 = fmaxf(mt0, __shfl_xor_sync(0xffffffffu, mt0, 1));
        mt0 = fmaxf(mt0, __shfl_xor_sync(0xffffffffu, mt0, 2));
        mt1 = fmaxf(mt1, __shfl_xor_sync(0xffffffffu, mt1, 1));
        mt1 = fmaxf(mt1, __shfl_xor_sync(0xffffffffu, mt1, 2));

        float mn0 = fmaxf(m0, mt0), mn1 = fmaxf(m1, mt1);
        float c0 = ex2f(m0 - mn0), c1 = ex2f(m1 - mn1);
        m0 = mn0; m1 = mn1;
        l0 *= c0; l1 *= c1;

        uint32_t pha[4][4], pla[4][4];
        #pragma unroll
        for (int nt = 0; nt < 8; nt++) {
            float p0 = ex2f(sc[nt][0] - m0);
            float p1 = ex2f(sc[nt][1] - m0);
            float p2 = ex2f(sc[nt][2] - m1);
            float p3 = ex2f(sc[nt][3] - m1);
            l0 += p0 + p1;
            l1 += p2 + p3;
            bf16 b0 = __float2bfloat16(p0), b1 = __float2bfloat16(p1);
            bf16 b2 = __float2bfloat16(p2), b3 = __float2bfloat16(p3);
            int kk = nt >> 1, hf = nt & 1;
            pha[kk][hf * 2 + 0] = pack2(p0, p1);
            pha[kk][hf * 2 + 1] = pack2(p2, p3);
            pla[kk][hf * 2 + 0] = pack2(p0 - __bfloat162float(b0), p1 - __bfloat162float(b1));
            pla[kk][hf * 2 + 1] = pack2(p2 - __bfloat162float(b2), p3 - __bfloat162float(b3));
        }

        #pragma unroll
        for (int nt = 0; nt < 8; nt++) {
            o[nt][0] *= c0; o[nt][1] *= c0;
            o[nt][2] *= c1; o[nt][3] *= c1;
        }

        // ---- O += P.V (bf16x3); V tiles are dim-major
        #pragma unroll
        for (int kk = 0; kk < 4; kk++) {
            #pragma unroll
            for (int nt = 0; nt < 8; nt++) {
                const uint32_t* vr  = (const uint32_t*)(svh + (nt * 8 + g) * KSTR + kk * 16 + 2 * q);
                const uint32_t* vlr = (const uint32_t*)(svl + (nt * 8 + g) * KSTR + kk * 16 + 2 * q);
                uint32_t vb[2]  = { vr[0],  vr[4]  };
                uint32_t vlb[2] = { vlr[0], vlr[4] };
                mma_bf16(o[nt], pha[kk], vb);
                mma_bf16(o[nt], pha[kk], vlb);
                mma_bf16(o[nt], pla[kk], vb);
            }
        }
    }

    // ---- finalize
    l0 += __shfl_xor_sync(0xffffffffu, l0, 1);
    l0 += __shfl_xor_sync(0xffffffffu, l0, 2);
    l1 += __shfl_xor_sync(0xffffffffu, l1, 1);
    l1 += __shfl_xor_sync(0xffffffffu, l1, 2);
    const float inv0 = 1.0f / l0, inv1 = 1.0f / l1;

    float* op0 = outp + ((size_t)(b * NSEQ + r0)) * DIM + h * HD;
    float* op1 = outp + ((size_t)(b * NSEQ + r0 + 8)) * DIM + h * HD;
    #pragma unroll
    for (int nt = 0; nt < 8; nt++) {
        *(float2*)(op0 + nt * 8 + 2 * q) = make_float2(o[nt][0] * inv0, o[nt][1] * inv0);
        *(float2*)(op1 + nt * 8 + 2 * q) = make_float2(o[nt][2] * inv1, o[nt][3] * inv1);
    }
}

// ------------------------------------------------------------------- launch
static inline void run_split(const float* src, bf16* hi, bf16* lo, size_t n) {
    int n4 = (int)(n / 4);
    split_kernel<<<(n4 + 255) / 256, 256>>>(src, hi, lo, n4);
}

extern "C" void kernel_launch(void* const* d_in, const int* in_sizes, int n_in,
                              void* d_out, int out_size)
{
    const float* x       = (const float*)d_in[0];
    const float* Wqkv    = (const float*)d_in[1];
    const float* Aqkv    = (const float*)d_in[2];
    const float* Bqkv    = (const float*)d_in[3];
    const float* Wproj   = (const float*)d_in[4];
    const float* Aproj   = (const float*)d_in[5];
    const float* Bproj   = (const float*)d_in[6];
    const int*   experts = (const int*)d_in[7];
    float*       out     = (float*)d_out;

    int estride = (in_sizes[7] >= 2 * NCHUNKS) ? 2 : 1;

    float *qkv_p, *o_p;
    bf16 *xh, *xl, *oh, *ol, *wqh, *wql, *wph, *wpl;
    bf16 *bqh, *bql, *bph, *bpl, *hh, *hl;
    bf16 *qah, *qal, *kah, *kal, *vth, *vtl;
    cudaGetSymbolAddress((void**)&qkv_p, g_qkv);
    cudaGetSymbolAddress((void**)&o_p,   g_o);
    cudaGetSymbolAddress((void**)&xh,  g_xh);  cudaGetSymbolAddress((void**)&xl,  g_xl);
    cudaGetSymbolAddress((void**)&oh,  g_oh);  cudaGetSymbolAddress((void**)&ol,  g_ol);
    cudaGetSymbolAddress((void**)&wqh, g_wqh); cudaGetSymbolAddress((void**)&wql, g_wql);
    cudaGetSymbolAddress((void**)&wph, g_wph); cudaGetSymbolAddress((void**)&wpl, g_wpl);
    cudaGetSymbolAddress((void**)&bqh, g_bqh); cudaGetSymbolAddress((void**)&bql, g_bql);
    cudaGetSymbolAddress((void**)&bph, g_bph); cudaGetSymbolAddress((void**)&bpl, g_bpl);
    cudaGetSymbolAddress((void**)&hh,  g_hh);  cudaGetSymbolAddress((void**)&hl,  g_hl);
    cudaGetSymbolAddress((void**)&qah, g_qah); cudaGetSymbolAddress((void**)&qal, g_qal);
    cudaGetSymbolAddress((void**)&kah, g_kah); cudaGetSymbolAddress((void**)&kal, g_kal);
    cudaGetSymbolAddress((void**)&vth, g_vth); cudaGetSymbolAddress((void**)&vtl, g_vtl);

    cudaFuncSetAttribute(mma_gemm, cudaFuncAttributeMaxDynamicSharedMemorySize, MMG_SMEM);

    // 0) split fp32 operands into bf16 hi/lo
    run_split(x,     xh,  xl,  (size_t)TOKENS * DIM);
    run_split(Wqkv,  wqh, wql, (size_t)QKV_DIM * DIM);
    run_split(Bqkv,  bqh, bql, (size_t)NEXP * QKV_DIM * RR);
    run_split(Wproj, wph, wpl, (size_t)DIM * DIM);
    run_split(Bproj, bph, bpl, (size_t)NEXP * DIM * RR);

    // 1) H = split(LSCALE * x @ Aqkv[e]^T)
    lora_h_kernel<<<TOKENS / 32, 256>>>(x, Aqkv, hh, hl, experts, estride);

    // 2) QKV = x @ Wqkv^T + H @ Bqkv[e]^T (bf16x3 HMMA)
    {
        dim3 grid(QKV_DIM / 128, TOKENS / 128);
        mma_gemm<<<grid, 256, MMG_SMEM>>>(xh, xl, wqh, wql, hh, hl, bqh, bql,
                                          qkv_p, QKV_DIM, experts, estride);
    }

    // 3) prep attention operands (Q/K split, V split+transpose)
    prep_qk<<<(TOKENS * (DIM / 4) + 255) / 256, 256>>>(qkv_p, qah, qal, kah, kal);
    {
        dim3 grid(NSEQ / 64, BB * HEADS);
        prep_vt<<<grid, 256>>>(qkv_p, vth, vtl);
    }

    // 4) tensor-core chunked block-causal attention
    {
        dim3 grid(CHUNK / 64, BB * HEADS, NCHUNKS);
        attn_mma<<<grid, 128>>>(qah, qal, kah, kal, vth, vtl, o_p);
    }

    // 5) split o; H2 = split(LSCALE * o @ Aproj[e]^T)
    run_split(o_p, oh, ol, (size_t)TOKENS * DIM);
    lora_h_kernel<<<TOKENS / 32, 256>>>(o_p, Aproj, hh, hl, experts, estride);

    // 6) out = o @ Wproj^T + H2 @ Bproj[e]^T (bf16x3 HMMA)
    {
        dim3 grid(DIM / 128, TOKENS / 128);
        mma_gemm<<<grid, 256, MMG_SMEM>>>(oh, ol, wph, wpl, hh, hl, bph, bpl,
                                          out, DIM, experts, estride);
    }
}

// round 8
// speedup vs baseline: 8.1902x; 1.1134x over previous
#include <cuda_runtime.h>
#include <cuda_bf16.h>
#include <cstdint>
#include <cstddef>

#define DIM     768
#define HEADS   12
#define HD      64
#define RR      64
#define BB      2
#define NSEQ    4096
#define CHUNK   1024
#define NCHUNKS 4
#define TOKENS  (BB*NSEQ)     // 8192
#define QKV_DIM (3*DIM)       // 2304
#define NEXP    8
#define LSCALE  2.0f          // 128 / 64
#define ATT_SCALE 0.125f      // 64^-0.5
#define LOG2E   1.4426950408889634f

typedef __nv_bfloat16 bf16;

// ------------------------------------------------------------------ scratch
__device__ float g_qkv[(size_t)TOKENS * QKV_DIM];   // fp32 q|k|v per token
__device__ float g_o  [(size_t)TOKENS * DIM];       // attention output fp32

// bf16 hi/lo split buffers (GEMM operands)
__device__ __align__(16) bf16 g_xh [(size_t)TOKENS * DIM],   g_xl [(size_t)TOKENS * DIM];
__device__ __align__(16) bf16 g_oh [(size_t)TOKENS * DIM],   g_ol [(size_t)TOKENS * DIM];
__device__ __align__(16) bf16 g_wqh[(size_t)QKV_DIM * DIM],  g_wql[(size_t)QKV_DIM * DIM];
__device__ __align__(16) bf16 g_wph[(size_t)DIM * DIM],      g_wpl[(size_t)DIM * DIM];
__device__ __align__(16) bf16 g_bqh[(size_t)NEXP * QKV_DIM * RR], g_bql[(size_t)NEXP * QKV_DIM * RR];
__device__ __align__(16) bf16 g_bph[(size_t)NEXP * DIM * RR],     g_bpl[(size_t)NEXP * DIM * RR];
__device__ __align__(16) bf16 g_aqh[(size_t)NEXP * RR * DIM],     g_aql[(size_t)NEXP * RR * DIM];
__device__ __align__(16) bf16 g_aph[(size_t)NEXP * RR * DIM],     g_apl[(size_t)NEXP * RR * DIM];
__device__ __align__(16) bf16 g_hh [(size_t)TOKENS * RR],    g_hl [(size_t)TOKENS * RR];

// attention operands: per (b,h) head-major layouts
__device__ __align__(16) bf16 g_qah[(size_t)BB*HEADS*NSEQ*HD], g_qal[(size_t)BB*HEADS*NSEQ*HD];
__device__ __align__(16) bf16 g_kah[(size_t)BB*HEADS*NSEQ*HD], g_kal[(size_t)BB*HEADS*NSEQ*HD];
__device__ __align__(16) bf16 g_vth[(size_t)BB*HEADS*HD*NSEQ], g_vtl[(size_t)BB*HEADS*HD*NSEQ];

// ------------------------------------------------------------------ helpers
__device__ __forceinline__ float ex2f(float x) {
    float y; asm("ex2.approx.f32 %0, %1;" : "=f"(y) : "f"(x)); return y;
}
__device__ __forceinline__ uint32_t s2u(const void* p) {
    uint32_t a;
    asm("{ .reg .u64 t; cvta.to.shared.u64 t, %1; cvt.u32.u64 %0, t; }" : "=r"(a) : "l"(p));
    return a;
}
__device__ __forceinline__ void cpa16(uint32_t d, const void* s) {
    asm volatile("cp.async.cg.shared.global [%0], [%1], 16;" :: "r"(d), "l"(s));
}
#define CP_COMMIT() asm volatile("cp.async.commit_group;" ::: "memory")
#define CP_WAIT1()  asm volatile("cp.async.wait_group 1;" ::: "memory")
#define CP_WAIT0()  asm volatile("cp.async.wait_group 0;" ::: "memory")

__device__ __forceinline__ void mma_bf16(float* d, const uint32_t* a, const uint32_t* b) {
    asm volatile(
        "mma.sync.aligned.m16n8k16.row.col.f32.bf16.bf16.f32 "
        "{%0,%1,%2,%3}, {%4,%5,%6,%7}, {%8,%9}, {%0,%1,%2,%3};"
        : "+f"(d[0]), "+f"(d[1]), "+f"(d[2]), "+f"(d[3])
        : "r"(a[0]), "r"(a[1]), "r"(a[2]), "r"(a[3]), "r"(b[0]), "r"(b[1]));
}
__device__ __forceinline__ void ldm_x4(uint32_t* r, uint32_t a) {
    asm volatile("ldmatrix.sync.aligned.m8n8.x4.shared.b16 {%0,%1,%2,%3}, [%4];"
        : "=r"(r[0]), "=r"(r[1]), "=r"(r[2]), "=r"(r[3]) : "r"(a));
}
__device__ __forceinline__ uint32_t pack2(float a, float b) {
    __nv_bfloat162 t = __floats2bfloat162_rn(a, b);
    return *(uint32_t*)&t;
}
__device__ __forceinline__ int expert_of(const int* ex, int chunk, int estride) {
    return ex[chunk * estride];
}

// ------------------------------------------------------------------ split
__global__ void __launch_bounds__(256) split_kernel(
    const float* __restrict__ src, bf16* __restrict__ hi,
    bf16* __restrict__ lo, int n4)
{
    int i = blockIdx.x * blockDim.x + threadIdx.x;
    if (i >= n4) return;
    float4 v = *(const float4*)(src + (size_t)i * 4);
    bf16 h0 = __float2bfloat16(v.x), h1 = __float2bfloat16(v.y);
    bf16 h2 = __float2bfloat16(v.z), h3 = __float2bfloat16(v.w);
    *(uint32_t*)(hi + (size_t)i * 4)     = pack2(v.x, v.y);
    *(uint32_t*)(hi + (size_t)i * 4 + 2) = pack2(v.z, v.w);
    *(uint32_t*)(lo + (size_t)i * 4)     = pack2(v.x - __bfloat162float(h0), v.y - __bfloat162float(h1));
    *(uint32_t*)(lo + (size_t)i * 4 + 2) = pack2(v.z - __bfloat162float(h2), v.w - __bfloat162float(h3));
}

// ------------------------------------------- shared tiling constants
#define KCH      32
#define RPADB    80                  // smem row stride bytes (32 bf16 + pad)
#define ARRB     (128*RPADB)
#define STAGEB   (4*ARRB)
#define NCH_MAIN (DIM/KCH)           // 24
#define NCH_TOT  (NCH_MAIN + 2)
#define MMG_SMEM (2*STAGEB)          // 81920

extern __shared__ char dynsmem[];

// ------------------------------------------- mma.sync bf16x3 fused GEMM
__global__ void __launch_bounds__(256, 1) mma_gemm(
    const bf16* __restrict__ Ah, const bf16* __restrict__ Al,
    const bf16* __restrict__ Wh, const bf16* __restrict__ Wl,
    const bf16* __restrict__ Hh, const bf16* __restrict__ Hl,
    const bf16* __restrict__ Blh, const bf16* __restrict__ Bll,
    float* __restrict__ C, int N, const int* __restrict__ experts, int estride)
{
    const int tid = threadIdx.x;
    const int lid = tid & 31;
    const int wid = tid >> 5;
    const int wm  = wid & 3;
    const int wn  = wid >> 2;
    const int g   = lid >> 2;
    const int q   = lid & 3;
    const int m0  = blockIdx.y * 128;
    const int n0  = blockIdx.x * 128;
    const int e   = expert_of(experts, (m0 % NSEQ) / CHUNK, estride);

    const bf16* beh = Blh + (size_t)e * N * RR;
    const bf16* bel = Bll + (size_t)e * N * RR;

    const uint32_t smem_u = s2u(dynsmem);

    // ldmatrix lane->address components
    const int aRow  = lid & 15;
    const int aHalf = lid >> 4;
    const int bN    = ((lid >> 4) & 1) * 8 + (lid & 7);
    const int bHalf = (lid >> 3) & 1;

    float acc[2][8][4] = {};

    auto issue_load = [&](int c, int s) {
        const bf16 *sa_h, *sa_l, *sb_h, *sb_l;
        int k0, rs;
        if (c < NCH_MAIN) { sa_h = Ah; sa_l = Al; sb_h = Wh;  sb_l = Wl;
                            k0 = c * KCH; rs = DIM; }
        else              { sa_h = Hh; sa_l = Hl; sb_h = beh; sb_l = bel;
                            k0 = (c - NCH_MAIN) * KCH; rs = RR; }
        uint32_t sb = smem_u + s * STAGEB;
        #pragma unroll
        for (int i = 0; i < 2; i++) {
            int idx = tid + i * 256;
            int r   = idx >> 2;
            int cc  = idx & 3;
            uint32_t doff = (uint32_t)(r * RPADB + cc * 16);
            size_t  aoff  = (size_t)(m0 + r) * rs + k0 + cc * 8;
            size_t  boff  = (size_t)(n0 + r) * rs + k0 + cc * 8;
            cpa16(sb + 0 * ARRB + doff, sa_h + aoff);
            cpa16(sb + 1 * ARRB + doff, sa_l + aoff);
            cpa16(sb + 2 * ARRB + doff, sb_h + boff);
            cpa16(sb + 3 * ARRB + doff, sb_l + boff);
        }
    };

    issue_load(0, 0);
    CP_COMMIT();

    for (int c = 0; c < NCH_TOT; c++) {
        const int s = c & 1;
        if (c + 1 < NCH_TOT) { issue_load(c + 1, s ^ 1); CP_COMMIT(); CP_WAIT1(); }
        else                 { CP_WAIT0(); }
        __syncthreads();

        const uint32_t sb = smem_u + s * STAGEB;

        #pragma unroll
        for (int k16 = 0; k16 < KCH / 16; k16++) {
            uint32_t ah[2][4], al[2][4], bh[8][2], bl[8][2];
            #pragma unroll
            for (int mt = 0; mt < 2; mt++) {
                uint32_t ad = sb + (uint32_t)((wm * 32 + mt * 16 + aRow) * RPADB + k16 * 32 + aHalf * 16);
                ldm_x4(ah[mt], ad);
                ldm_x4(al[mt], ad + ARRB);
            }
            #pragma unroll
            for (int j = 0; j < 4; j++) {
                uint32_t bd = sb + 2 * ARRB +
                    (uint32_t)((wn * 64 + j * 16 + bN) * RPADB + k16 * 32 + bHalf * 16);
                uint32_t t0[4], t1[4];
                ldm_x4(t0, bd);
                ldm_x4(t1, bd + ARRB);
                bh[2 * j][0] = t0[0]; bh[2 * j][1] = t0[1];
                bh[2 * j + 1][0] = t0[2]; bh[2 * j + 1][1] = t0[3];
                bl[2 * j][0] = t1[0]; bl[2 * j][1] = t1[1];
                bl[2 * j + 1][0] = t1[2]; bl[2 * j + 1][1] = t1[3];
            }
            #pragma unroll
            for (int mt = 0; mt < 2; mt++)
                #pragma unroll
                for (int nt = 0; nt < 8; nt++)
                    mma_bf16(acc[mt][nt], ah[mt], bh[nt]);
            #pragma unroll
            for (int mt = 0; mt < 2; mt++)
                #pragma unroll
                for (int nt = 0; nt < 8; nt++)
                    mma_bf16(acc[mt][nt], ah[mt], bl[nt]);
            #pragma unroll
            for (int mt = 0; mt < 2; mt++)
                #pragma unroll
                for (int nt = 0; nt < 8; nt++)
                    mma_bf16(acc[mt][nt], al[mt], bh[nt]);
        }
        __syncthreads();
    }

    #pragma unroll
    for (int mt = 0; mt < 2; mt++) {
        int row = m0 + wm * 32 + mt * 16 + g;
        #pragma unroll
        for (int nt = 0; nt < 8; nt++) {
            int col = n0 + wn * 64 + nt * 8 + q * 2;
            *(float2*)(C + (size_t)row * N + col) =
                make_float2(acc[mt][nt][0], acc[mt][nt][1]);
            *(float2*)(C + (size_t)(row + 8) * N + col) =
                make_float2(acc[mt][nt][2], acc[mt][nt][3]);
        }
    }
}

// ------------------------------------------- HMMA LoRA-A: H = split(LSCALE * A @ Ae^T)
// A = split tokens (M x 768), Ae = split Aqkv/Aproj expert slice (64 x 768).
// Block 128 rows, 8 warps (16 rows each), N = 64 full width.
#define LARRA (128*RPADB)            // 10240
#define LARRB (64*RPADB)             // 5120
#define LSTG  (2*LARRA + 2*LARRB)    // 30720
#define LORA_SMEM (2*LSTG)           // 61440
#define LNCH  (DIM/KCH)              // 24

__global__ void __launch_bounds__(256, 1) lora_mma(
    const bf16* __restrict__ Ah, const bf16* __restrict__ Al,
    const bf16* __restrict__ Aeh, const bf16* __restrict__ Ael,
    bf16* __restrict__ Ch, bf16* __restrict__ Cl,
    const int* __restrict__ experts, int estride)
{
    const int tid = threadIdx.x;
    const int lid = tid & 31;
    const int wid = tid >> 5;
    const int g   = lid >> 2;
    const int q   = lid & 3;
    const int m0  = blockIdx.x * 128;
    const int e   = expert_of(experts, (m0 % NSEQ) / CHUNK, estride);

    const bf16* Beh = Aeh + (size_t)e * RR * DIM;
    const bf16* Bel = Ael + (size_t)e * RR * DIM;

    const uint32_t smem_u = s2u(dynsmem);
    const int aRow  = lid & 15;
    const int aHalf = lid >> 4;
    const int bN    = ((lid >> 4) & 1) * 8 + (lid & 7);
    const int bHalf = (lid >> 3) & 1;

    float acc[8][4] = {};

    auto issue_load = [&](int c, int s) {
        int k0 = c * KCH;
        uint32_t sb = smem_u + s * LSTG;
        #pragma unroll
        for (int i = 0; i < 2; i++) {          // A: 128 rows x 4 chunks
            int idx = tid + i * 256;
            int r = idx >> 2, cc = idx & 3;
            uint32_t doff = (uint32_t)(r * RPADB + cc * 16);
            size_t aoff = (size_t)(m0 + r) * DIM + k0 + cc * 8;
            cpa16(sb + doff,         Ah + aoff);
            cpa16(sb + LARRA + doff, Al + aoff);
        }
        {                                       // B: 64 rows x 4 chunks
            int r = tid >> 2, cc = tid & 3;
            if (r < 64) {
                uint32_t doff = (uint32_t)(r * RPADB + cc * 16);
                size_t boff = (size_t)r * DIM + k0 + cc * 8;
                cpa16(sb + 2 * LARRA + doff,         Beh + boff);
                cpa16(sb + 2 * LARRA + LARRB + doff, Bel + boff);
            }
        }
    };

    issue_load(0, 0);
    CP_COMMIT();

    for (int c = 0; c < LNCH; c++) {
        const int s = c & 1;
        if (c + 1 < LNCH) { issue_load(c + 1, s ^ 1); CP_COMMIT(); CP_WAIT1(); }
        else              { CP_WAIT0(); }
        __syncthreads();

        const uint32_t sb = smem_u + s * LSTG;
        #pragma unroll
        for (int k16 = 0; k16 < KCH / 16; k16++) {
            uint32_t ah[4], al[4], bh[8][2], bl[8][2];
            {
                uint32_t ad = sb + (uint32_t)((wid * 16 + aRow) * RPADB + k16 * 32 + aHalf * 16);
                ldm_x4(ah, ad);
                ldm_x4(al, ad + LARRA);
            }
            #pragma unroll
            for (int j = 0; j < 4; j++) {
                uint32_t bd = sb + 2 * LARRA +
                    (uint32_t)((j * 16 + bN) * RPADB + k16 * 32 + bHalf * 16);
                uint32_t t0[4], t1[4];
                ldm_x4(t0, bd);
                ldm_x4(t1, bd + LARRB);
                bh[2 * j][0] = t0[0]; bh[2 * j][1] = t0[1];
                bh[2 * j + 1][0] = t0[2]; bh[2 * j + 1][1] = t0[3];
                bl[2 * j][0] = t1[0]; bl[2 * j][1] = t1[1];
                bl[2 * j + 1][0] = t1[2]; bl[2 * j + 1][1] = t1[3];
            }
            #pragma unroll
            for (int nt = 0; nt < 8; nt++) mma_bf16(acc[nt], ah, bh[nt]);
            #pragma unroll
            for (int nt = 0; nt < 8; nt++) mma_bf16(acc[nt], ah, bl[nt]);
            #pragma unroll
            for (int nt = 0; nt < 8; nt++) mma_bf16(acc[nt], al, bh[nt]);
        }
        __syncthreads();
    }

    // epilogue: v = LSCALE * acc, write split hi/lo
    const int row0 = m0 + wid * 16 + g;
    #pragma unroll
    for (int nt = 0; nt < 8; nt++) {
        int col = nt * 8 + q * 2;
        #pragma unroll
        for (int half = 0; half < 2; half++) {
            int row = row0 + half * 8;
            float v0 = acc[nt][half * 2 + 0] * LSCALE;
            float v1 = acc[nt][half * 2 + 1] * LSCALE;
            bf16 h0 = __float2bfloat16(v0), h1 = __float2bfloat16(v1);
            *(uint32_t*)(Ch + (size_t)row * RR + col) = pack2(v0, v1);
            *(uint32_t*)(Cl + (size_t)row * RR + col) =
                pack2(v0 - __bfloat162float(h0), v1 - __bfloat162float(h1));
        }
    }
}

// ------------------------------------------------------------- attn prep
__global__ void __launch_bounds__(256) prep_qk(
    const float* __restrict__ qkv,
    bf16* __restrict__ Qh, bf16* __restrict__ Ql,
    bf16* __restrict__ Kh, bf16* __restrict__ Kl)
{
    int i4 = blockIdx.x * 256 + threadIdx.x;
    if (i4 >= TOKENS * (DIM / 4)) return;
    int t  = i4 / (DIM / 4);
    int j  = i4 % (DIM / 4);
    int h  = j >> 4;
    int d4 = j & 15;
    int b  = t >> 12, n = t & (NSEQ - 1);

    const float* qp = qkv + (size_t)t * QKV_DIM + h * HD + d4 * 4;
    float4 qv = *(const float4*)qp;
    float4 kv = *(const float4*)(qp + DIM);
    size_t dst = ((size_t)(b * HEADS + h) * NSEQ + n) * HD + d4 * 4;

    const float qs = ATT_SCALE * LOG2E;
    float q0 = qv.x * qs, q1 = qv.y * qs, q2 = qv.z * qs, q3 = qv.w * qs;

    bf16 h0 = __float2bfloat16(q0), h1 = __float2bfloat16(q1);
    bf16 h2 = __float2bfloat16(q2), h3 = __float2bfloat16(q3);
    *(uint32_t*)(Qh + dst)     = pack2(q0, q1);
    *(uint32_t*)(Qh + dst + 2) = pack2(q2, q3);
    *(uint32_t*)(Ql + dst)     = pack2(q0 - __bfloat162float(h0), q1 - __bfloat162float(h1));
    *(uint32_t*)(Ql + dst + 2) = pack2(q2 - __bfloat162float(h2), q3 - __bfloat162float(h3));

    bf16 k0 = __float2bfloat16(kv.x), k1 = __float2bfloat16(kv.y);
    bf16 k2 = __float2bfloat16(kv.z), k3 = __float2bfloat16(kv.w);
    *(uint32_t*)(Kh + dst)     = pack2(kv.x, kv.y);
    *(uint32_t*)(Kh + dst + 2) = pack2(kv.z, kv.w);
    *(uint32_t*)(Kl + dst)     = pack2(kv.x - __bfloat162float(k0), kv.y - __bfloat162float(k1));
    *(uint32_t*)(Kl + dst + 2) = pack2(kv.z - __bfloat162float(k2), kv.w - __bfloat162float(k3));
}

__global__ void __launch_bounds__(256) prep_vt(
    const float* __restrict__ qkv, bf16* __restrict__ Vth, bf16* __restrict__ Vtl)
{
    __shared__ float vsm[64][65];
    const int n0 = blockIdx.x * 64;
    const int bh = blockIdx.y;
    const int b = bh / HEADS, h = bh % HEADS;
    const int tid = threadIdx.x;

    #pragma unroll
    for (int i = 0; i < 16; i++) {
        int idx = tid + i * 256;
        int r = idx >> 6, d = idx & 63;
        vsm[r][d] = qkv[((size_t)(b * NSEQ + n0 + r)) * QKV_DIM + 2 * DIM + h * HD + d];
    }
    __syncthreads();
    #pragma unroll
    for (int i = 0; i < 16; i++) {
        int idx = tid + i * 256;
        int d = idx >> 6, t = idx & 63;
        float v = vsm[t][d];
        bf16 hh = __float2bfloat16(v);
        size_t o = ((size_t)bh * HD + d) * NSEQ + n0 + t;
        Vth[o] = hh;
        Vtl[o] = __float2bfloat16(v - __bfloat162float(hh));
    }
}

// ------------------------------------------ tensor-core flash attention
// Block: 128 q-rows, 8 warps (16 q-rows each), 64-key tiles, double-buffered.
#define KSTR      72                  // row stride in bf16 elems (144B)
#define ATT_TILE  (64*KSTR*2)         // 9216 B per operand array
#define ATT_STAGE (4*ATT_TILE)        // kh | kl | vh | vl
#define ATT_SMEM  (2*ATT_STAGE)       // 73728

__global__ void __launch_bounds__(256, 1) attn_mma(
    const bf16* __restrict__ Qh, const bf16* __restrict__ Ql,
    const bf16* __restrict__ Kh, const bf16* __restrict__ Kl,
    const bf16* __restrict__ Vth, const bf16* __restrict__ Vtl,
    float* __restrict__ outp)
{
    const int qt    = blockIdx.x;
    const int bh    = blockIdx.y;
    const int chunk = (NCHUNKS - 1) - blockIdx.z;   // heavy first
    const int b     = bh / HEADS, h = bh % HEADS;
    const int tid   = threadIdx.x;
    const int w     = tid >> 5, lid = tid & 31;
    const int g     = lid >> 2, q = lid & 3;
    const int klend = (chunk + 1) * CHUNK;

    const bf16* Qbh  = Qh  + (size_t)bh * NSEQ * HD;
    const bf16* Qlbh = Ql  + (size_t)bh * NSEQ * HD;
    const bf16* Kbh  = Kh  + (size_t)bh * NSEQ * HD;
    const bf16* Klbh = Kl  + (size_t)bh * NSEQ * HD;
    const bf16* Vbh  = Vth + (size_t)bh * HD * NSEQ;
    const bf16* Vlbh = Vtl + (size_t)bh * HD * NSEQ;

    const int r0 = chunk * CHUNK + qt * 128 + w * 16 + g;

    // Q fragments resident for the whole block
    uint32_t qhf[4][4], qlf[4][4];
    #pragma unroll
    for (int kk = 0; kk < 4; kk++) {
        size_t base0 = (size_t)r0 * HD + kk * 16 + 2 * q;
        size_t base1 = (size_t)(r0 + 8) * HD + kk * 16 + 2 * q;
        qhf[kk][0] = *(const uint32_t*)(Qbh + base0);
        qhf[kk][1] = *(const uint32_t*)(Qbh + base1);
        qhf[kk][2] = *(const uint32_t*)(Qbh + base0 + 8);
        qhf[kk][3] = *(const uint32_t*)(Qbh + base1 + 8);
        qlf[kk][0] = *(const uint32_t*)(Qlbh + base0);
        qlf[kk][1] = *(const uint32_t*)(Qlbh + base1);
        qlf[kk][2] = *(const uint32_t*)(Qlbh + base0 + 8);
        qlf[kk][3] = *(const uint32_t*)(Qlbh + base1 + 8);
    }

    const uint32_t smem_u = s2u(dynsmem);
    const int bN    = ((lid >> 4) & 1) * 8 + (lid & 7);
    const int bHalf = (lid >> 3) & 1;

    float o[8][4] = {};
    float m0 = -1e30f, m1 = -1e30f, l0 = 0.f, l1 = 0.f;

    auto load_tile = [&](int kt, int s) {
        uint32_t base = smem_u + s * ATT_STAGE;
        #pragma unroll
        for (int i = 0; i < 2; i++) {
            int idx = tid + i * 256;            // 0..511 = 64 rows x 8 chunks
            int r = idx >> 3, c = idx & 7;
            uint32_t doff = (uint32_t)(r * KSTR + c * 8) * 2;
            cpa16(base + 0 * ATT_TILE + doff, Kbh  + (size_t)(kt + r) * HD + c * 8);
            cpa16(base + 1 * ATT_TILE + doff, Klbh + (size_t)(kt + r) * HD + c * 8);
            cpa16(base + 2 * ATT_TILE + doff, Vbh  + (size_t)r * NSEQ + kt + c * 8);
            cpa16(base + 3 * ATT_TILE + doff, Vlbh + (size_t)r * NSEQ + kt + c * 8);
        }
    };

    const int ntile = klend >> 6;
    load_tile(0, 0);
    CP_COMMIT();

    for (int t = 0; t < ntile; t++) {
        const int s = t & 1;
        if (t + 1 < ntile) { load_tile((t + 1) << 6, s ^ 1); CP_COMMIT(); CP_WAIT1(); }
        else               { CP_WAIT0(); }
        __syncthreads();

        const uint32_t sbK = smem_u + s * ATT_STAGE;
        const uint32_t sbV = sbK + 2 * ATT_TILE;

        // ---- scores S = Q.K^T (bf16x3)
        float sc[8][4] = {};
        #pragma unroll
        for (int kk = 0; kk < 4; kk++) {
            uint32_t kb[8][2], klb[8][2];
            #pragma unroll
            for (int j = 0; j < 4; j++) {
                uint32_t kd = sbK + (uint32_t)((j * 16 + bN) * KSTR * 2 + kk * 32 + bHalf * 16);
                uint32_t t0[4], t1[4];
                ldm_x4(t0, kd);
                ldm_x4(t1, kd + ATT_TILE);
                kb[2 * j][0] = t0[0]; kb[2 * j][1] = t0[1];
                kb[2 * j + 1][0] = t0[2]; kb[2 * j + 1][1] = t0[3];
                klb[2 * j][0] = t1[0]; klb[2 * j][1] = t1[1];
                klb[2 * j + 1][0] = t1[2]; klb[2 * j + 1][1] = t1[3];
            }
            #pragma unroll
            for (int nt = 0; nt < 8; nt++) {
                mma_bf16(sc[nt], qhf[kk], kb[nt]);
                mma_bf16(sc[nt], qhf[kk], klb[nt]);
                mma_bf16(sc[nt], qlf[kk], kb[nt]);
            }
        }

        // ---- online softmax (exp2 domain)
        float mt0 = -1e30f, mt1 = -1e30f;
        #pragma unroll
        for (int nt = 0; nt < 8; nt++) {
            mt0 = fmaxf(mt0, fmaxf(sc[nt][0], sc[nt][1]));
            mt1 = fmaxf(mt1, fmaxf(sc[nt][2], sc[nt][3]));
        }
        mt0 = fmaxf(mt0, __shfl_xor_sync(0xffffffffu, mt0, 1));
        mt0 = fmaxf(mt0, __shfl_xor_sync(0xffffffffu, mt0, 2));
        mt1 = fmaxf(mt1, __shfl_xor_sync(0xffffffffu, mt1, 1));
        mt1 = fmaxf(mt1, __shfl_xor_sync(0xffffffffu, mt1, 2));

        float mn0 = fmaxf(m0, mt0), mn1 = fmaxf(m1, mt1);
        float c0 = ex2f(m0 - mn0), c1 = ex2f(m1 - mn1);
        m0 = mn0; m1 = mn1;
        l0 *= c0; l1 *= c1;

        uint32_t pha[4][4], pla[4][4];
        #pragma unroll
        for (int nt = 0; nt < 8; nt++) {
            float p0 = ex2f(sc[nt][0] - m0);
            float p1 = ex2f(sc[nt][1] - m0);
            float p2 = ex2f(sc[nt][2] - m1);
            float p3 = ex2f(sc[nt][3] - m1);
            l0 += p0 + p1;
            l1 += p2 + p3;
            bf16 b0 = __float2bfloat16(p0), b1 = __float2bfloat16(p1);
            bf16 b2 = __float2bfloat16(p2), b3 = __float2bfloat16(p3);
            int kk = nt >> 1, hf = nt & 1;
            pha[kk][hf * 2 + 0] = pack2(p0, p1);
            pha[kk][hf * 2 + 1] = pack2(p2, p3);
            pla[kk][hf * 2 + 0] = pack2(p0 - __bfloat162float(b0), p1 - __bfloat162float(b1));
            pla[kk][hf * 2 + 1] = pack2(p2 - __bfloat162float(b2), p3 - __bfloat162float(b3));
        }

        #pragma unroll
        for (int nt = 0; nt < 8; nt++) {
            o[nt][0] *= c0; o[nt][1] *= c0;
            o[nt][2] *= c1; o[nt][3] *= c1;
        }

        // ---- O += P.V (bf16x3)
        #pragma unroll
        for (int kk = 0; kk < 4; kk++) {
            uint32_t vb[8][2], vlb[8][2];
            #pragma unroll
            for (int j = 0; j < 4; j++) {
                uint32_t vd = sbV + (uint32_t)((j * 16 + bN) * KSTR * 2 + kk * 32 + bHalf * 16);
                uint32_t t0[4], t1[4];
                ldm_x4(t0, vd);
                ldm_x4(t1, vd + ATT_TILE);
                vb[2 * j][0] = t0[0]; vb[2 * j][1] = t0[1];
                vb[2 * j + 1][0] = t0[2]; vb[2 * j + 1][1] = t0[3];
                vlb[2 * j][0] = t1[0]; vlb[2 * j][1] = t1[1];
                vlb[2 * j + 1][0] = t1[2]; vlb[2 * j + 1][1] = t1[3];
            }
            #pragma unroll
            for (int nt = 0; nt < 8; nt++) {
                mma_bf16(o[nt], pha[kk], vb[nt]);
                mma_bf16(o[nt], pha[kk], vlb[nt]);
                mma_bf16(o[nt], pla[kk], vb[nt]);
            }
        }
        __syncthreads();
    }

    // ---- finalize
    l0 += __shfl_xor_sync(0xffffffffu, l0, 1);
    l0 += __shfl_xor_sync(0xffffffffu, l0, 2);
    l1 += __shfl_xor_sync(0xffffffffu, l1, 1);
    l1 += __shfl_xor_sync(0xffffffffu, l1, 2);
    const float inv0 = 1.0f / l0, inv1 = 1.0f / l1;

    float* op0 = outp + ((size_t)(b * NSEQ + r0)) * DIM + h * HD;
    float* op1 = outp + ((size_t)(b * NSEQ + r0 + 8)) * DIM + h * HD;
    #pragma unroll
    for (int nt = 0; nt < 8; nt++) {
        *(float2*)(op0 + nt * 8 + 2 * q) = make_float2(o[nt][0] * inv0, o[nt][1] * inv0);
        *(float2*)(op1 + nt * 8 + 2 * q) = make_float2(o[nt][2] * inv1, o[nt][3] * inv1);
    }
}

// ------------------------------------------------------------------- launch
static inline void run_split(const float* src, bf16* hi, bf16* lo, size_t n) {
    int n4 = (int)(n / 4);
    split_kernel<<<(n4 + 255) / 256, 256>>>(src, hi, lo, n4);
}

extern "C" void kernel_launch(void* const* d_in, const int* in_sizes, int n_in,
                              void* d_out, int out_size)
{
    const float* x       = (const float*)d_in[0];
    const float* Wqkv    = (const float*)d_in[1];
    const float* Aqkv    = (const float*)d_in[2];
    const float* Bqkv    = (const float*)d_in[3];
    const float* Wproj   = (const float*)d_in[4];
    const float* Aproj   = (const float*)d_in[5];
    const float* Bproj   = (const float*)d_in[6];
    const int*   experts = (const int*)d_in[7];
    float*       out     = (float*)d_out;

    int estride = (in_sizes[7] >= 2 * NCHUNKS) ? 2 : 1;

    float *qkv_p, *o_p;
    bf16 *xh, *xl, *oh, *ol, *wqh, *wql, *wph, *wpl;
    bf16 *bqh, *bql, *bph, *bpl, *aqh, *aql, *aph, *apl, *hh, *hl;
    bf16 *qah, *qal, *kah, *kal, *vth, *vtl;
    cudaGetSymbolAddress((void**)&qkv_p, g_qkv);
    cudaGetSymbolAddress((void**)&o_p,   g_o);
    cudaGetSymbolAddress((void**)&xh,  g_xh);  cudaGetSymbolAddress((void**)&xl,  g_xl);
    cudaGetSymbolAddress((void**)&oh,  g_oh);  cudaGetSymbolAddress((void**)&ol,  g_ol);
    cudaGetSymbolAddress((void**)&wqh, g_wqh); cudaGetSymbolAddress((void**)&wql, g_wql);
    cudaGetSymbolAddress((void**)&wph, g_wph); cudaGetSymbolAddress((void**)&wpl, g_wpl);
    cudaGetSymbolAddress((void**)&bqh, g_bqh); cudaGetSymbolAddress((void**)&bql, g_bql);
    cudaGetSymbolAddress((void**)&bph, g_bph); cudaGetSymbolAddress((void**)&bpl, g_bpl);
    cudaGetSymbolAddress((void**)&aqh, g_aqh); cudaGetSymbolAddress((void**)&aql, g_aql);
    cudaGetSymbolAddress((void**)&aph, g_aph); cudaGetSymbolAddress((void**)&apl, g_apl);
    cudaGetSymbolAddress((void**)&hh,  g_hh);  cudaGetSymbolAddress((void**)&hl,  g_hl);
    cudaGetSymbolAddress((void**)&qah, g_qah); cudaGetSymbolAddress((void**)&qal, g_qal);
    cudaGetSymbolAddress((void**)&kah, g_kah); cudaGetSymbolAddress((void**)&kal, g_kal);
    cudaGetSymbolAddress((void**)&vth, g_vth); cudaGetSymbolAddress((void**)&vtl, g_vtl);

    cudaFuncSetAttribute(mma_gemm, cudaFuncAttributeMaxDynamicSharedMemorySize, MMG_SMEM);
    cudaFuncSetAttribute(lora_mma, cudaFuncAttributeMaxDynamicSharedMemorySize, LORA_SMEM);
    cudaFuncSetAttribute(attn_mma, cudaFuncAttributeMaxDynamicSharedMemorySize, ATT_SMEM);

    // 0) split fp32 operands into bf16 hi/lo
    run_split(x,     xh,  xl,  (size_t)TOKENS * DIM);
    run_split(Wqkv,  wqh, wql, (size_t)QKV_DIM * DIM);
    run_split(Bqkv,  bqh, bql, (size_t)NEXP * QKV_DIM * RR);
    run_split(Wproj, wph, wpl, (size_t)DIM * DIM);
    run_split(Bproj, bph, bpl, (size_t)NEXP * DIM * RR);
    run_split(Aqkv,  aqh, aql, (size_t)NEXP * RR * DIM);
    run_split(Aproj, aph, apl, (size_t)NEXP * RR * DIM);

    // 1) H = split(LSCALE * x @ Aqkv[e]^T)  (HMMA)
    lora_mma<<<TOKENS / 128, 256, LORA_SMEM>>>(xh, xl, aqh, aql, hh, hl, experts, estride);

    // 2) QKV = x @ Wqkv^T + H @ Bqkv[e]^T (bf16x3 HMMA)
    {
        dim3 grid(QKV_DIM / 128, TOKENS / 128);
        mma_gemm<<<grid, 256, MMG_SMEM>>>(xh, xl, wqh, wql, hh, hl, bqh, bql,
                                          qkv_p, QKV_DIM, experts, estride);
    }

    // 3) prep attention operands
    prep_qk<<<(TOKENS * (DIM / 4) + 255) / 256, 256>>>(qkv_p, qah, qal, kah, kal);
    {
        dim3 grid(NSEQ / 64, BB * HEADS);
        prep_vt<<<grid, 256>>>(qkv_p, vth, vtl);
    }

    // 4) tensor-core chunked block-causal attention
    {
        dim3 grid(CHUNK / 128, BB * HEADS, NCHUNKS);
        attn_mma<<<grid, 256, ATT_SMEM>>>(qah, qal, kah, kal, vth, vtl, o_p);
    }

    // 5) split o; H2 = split(LSCALE * o @ Aproj[e]^T)  (HMMA)
    run_split(o_p, oh, ol, (size_t)TOKENS * DIM);
    lora_mma<<<TOKENS / 128, 256, LORA_SMEM>>>(oh, ol, aph, apl, hh, hl, experts, estride);

    // 6) out = o @ Wproj^T + H2 @ Bproj[e]^T (bf16x3 HMMA)
    {
        dim3 grid(DIM / 128, TOKENS / 128);
        mma_gemm<<<grid, 256, MMG_SMEM>>>(oh, ol, wph, wpl, hh, hl, bph, bpl,
                                          out, DIM, experts, estride);
    }
}

// round 9
// speedup vs baseline: 8.9031x; 1.0870x over previous
#include <cuda_runtime.h>
#include <cuda_bf16.h>
#include <cstdint>
#include <cstddef>

#define DIM     768
#define HEADS   12
#define HD      64
#define RR      64
#define BB      2
#define NSEQ    4096
#define CHUNK   1024
#define NCHUNKS 4
#define TOKENS  (BB*NSEQ)     // 8192
#define QKV_DIM (3*DIM)       // 2304
#define NEXP    8
#define LSCALE  2.0f          // 128 / 64
#define ATT_SCALE 0.125f      // 64^-0.5
#define LOG2E   1.4426950408889634f

typedef __nv_bfloat16 bf16;

// ------------------------------------------------------------------ scratch
// bf16 hi/lo split buffers (GEMM operands)
__device__ __align__(16) bf16 g_xh [(size_t)TOKENS * DIM],   g_xl [(size_t)TOKENS * DIM];
__device__ __align__(16) bf16 g_oh [(size_t)TOKENS * DIM],   g_ol [(size_t)TOKENS * DIM];
__device__ __align__(16) bf16 g_wqh[(size_t)QKV_DIM * DIM],  g_wql[(size_t)QKV_DIM * DIM];
__device__ __align__(16) bf16 g_wph[(size_t)DIM * DIM],      g_wpl[(size_t)DIM * DIM];
__device__ __align__(16) bf16 g_bqh[(size_t)NEXP * QKV_DIM * RR], g_bql[(size_t)NEXP * QKV_DIM * RR];
__device__ __align__(16) bf16 g_bph[(size_t)NEXP * DIM * RR],     g_bpl[(size_t)NEXP * DIM * RR];
__device__ __align__(16) bf16 g_aqh[(size_t)NEXP * RR * DIM],     g_aql[(size_t)NEXP * RR * DIM];
__device__ __align__(16) bf16 g_aph[(size_t)NEXP * RR * DIM],     g_apl[(size_t)NEXP * RR * DIM];
__device__ __align__(16) bf16 g_hh [(size_t)TOKENS * RR],    g_hl [(size_t)TOKENS * RR];

// attention operands: per (b,h) head-major layouts
__device__ __align__(16) bf16 g_qah[(size_t)BB*HEADS*NSEQ*HD], g_qal[(size_t)BB*HEADS*NSEQ*HD];
__device__ __align__(16) bf16 g_kah[(size_t)BB*HEADS*NSEQ*HD], g_kal[(size_t)BB*HEADS*NSEQ*HD];
__device__ __align__(16) bf16 g_vth[(size_t)BB*HEADS*HD*NSEQ], g_vtl[(size_t)BB*HEADS*HD*NSEQ];

// ------------------------------------------------------------------ helpers
__device__ __forceinline__ float ex2f(float x) {
    float y; asm("ex2.approx.f32 %0, %1;" : "=f"(y) : "f"(x)); return y;
}
__device__ __forceinline__ uint32_t s2u(const void* p) {
    uint32_t a;
    asm("{ .reg .u64 t; cvta.to.shared.u64 t, %1; cvt.u32.u64 %0, t; }" : "=r"(a) : "l"(p));
    return a;
}
__device__ __forceinline__ void cpa16(uint32_t d, const void* s) {
    asm volatile("cp.async.cg.shared.global [%0], [%1], 16;" :: "r"(d), "l"(s));
}
#define CP_COMMIT() asm volatile("cp.async.commit_group;" ::: "memory")
#define CP_WAIT1()  asm volatile("cp.async.wait_group 1;" ::: "memory")
#define CP_WAIT0()  asm volatile("cp.async.wait_group 0;" ::: "memory")

__device__ __forceinline__ void mma_bf16(float* d, const uint32_t* a, const uint32_t* b) {
    asm volatile(
        "mma.sync.aligned.m16n8k16.row.col.f32.bf16.bf16.f32 "
        "{%0,%1,%2,%3}, {%4,%5,%6,%7}, {%8,%9}, {%0,%1,%2,%3};"
        : "+f"(d[0]), "+f"(d[1]), "+f"(d[2]), "+f"(d[3])
        : "r"(a[0]), "r"(a[1]), "r"(a[2]), "r"(a[3]), "r"(b[0]), "r"(b[1]));
}
__device__ __forceinline__ void ldm_x4(uint32_t* r, uint32_t a) {
    asm volatile("ldmatrix.sync.aligned.m8n8.x4.shared.b16 {%0,%1,%2,%3}, [%4];"
        : "=r"(r[0]), "=r"(r[1]), "=r"(r[2]), "=r"(r[3]) : "r"(a));
}
__device__ __forceinline__ uint32_t pack2(float a, float b) {
    __nv_bfloat162 t = __floats2bfloat162_rn(a, b);
    return *(uint32_t*)&t;
}
__device__ __forceinline__ uint32_t pack2lo(float a, float b) {
    // residuals after bf16 hi rounding
    bf16 ha = __float2bfloat16(a), hb = __float2bfloat16(b);
    return pack2(a - __bfloat162float(ha), b - __bfloat162float(hb));
}
__device__ __forceinline__ int expert_of(const int* ex, int chunk, int estride) {
    return ex[chunk * estride];
}

// ------------------------------------------------------------------ split
__global__ void __launch_bounds__(256) split_kernel(
    const float* __restrict__ src, bf16* __restrict__ hi,
    bf16* __restrict__ lo, int n4)
{
    int i = blockIdx.x * blockDim.x + threadIdx.x;
    if (i >= n4) return;
    float4 v = *(const float4*)(src + (size_t)i * 4);
    *(uint32_t*)(hi + (size_t)i * 4)     = pack2(v.x, v.y);
    *(uint32_t*)(hi + (size_t)i * 4 + 2) = pack2(v.z, v.w);
    *(uint32_t*)(lo + (size_t)i * 4)     = pack2lo(v.x, v.y);
    *(uint32_t*)(lo + (size_t)i * 4 + 2) = pack2lo(v.z, v.w);
}

// ------------------------------------------- shared tiling constants
#define KCH      32
#define RPADB    80                  // smem row stride bytes (32 bf16 + pad)
#define ARRB     (128*RPADB)
#define STAGEB   (4*ARRB)
#define NCH_MAIN (DIM/KCH)           // 24
#define NCH_TOT  (NCH_MAIN + 2)
#define MMG_SMEM (2*STAGEB)          // 81920
#define VSTR     132                 // V transpose stage stride (floats)

extern __shared__ char dynsmem[];

// =========================================================================
// Shared mainloop macro body for 128x128 bf16x3 GEMM (A @ B^T + H @ Be^T).
// Produces acc[2][8][4] per thread. Caller provides epilogue.
// =========================================================================
struct GemmCtx {
    const bf16 *Ah, *Al, *Wh, *Wl, *Hh, *Hl, *beh, *bel;
    int m0, n0;
};

__device__ __forceinline__ void gemm_mainloop_128(
    const GemmCtx& cx, int tid, float acc[2][8][4])
{
    const int lid = tid & 31;
    const int wid = tid >> 5;
    const int wm  = wid & 3;
    const int wn  = wid >> 2;
    const uint32_t smem_u = s2u(dynsmem);

    const int aRow  = lid & 15;
    const int aHalf = lid >> 4;
    const int bN    = ((lid >> 4) & 1) * 8 + (lid & 7);
    const int bHalf = (lid >> 3) & 1;

    auto issue_load = [&](int c, int s) {
        const bf16 *sa_h, *sa_l, *sb_h, *sb_l;
        int k0, rs;
        if (c < NCH_MAIN) { sa_h = cx.Ah; sa_l = cx.Al; sb_h = cx.Wh;  sb_l = cx.Wl;
                            k0 = c * KCH; rs = DIM; }
        else              { sa_h = cx.Hh; sa_l = cx.Hl; sb_h = cx.beh; sb_l = cx.bel;
                            k0 = (c - NCH_MAIN) * KCH; rs = RR; }
        uint32_t sb = smem_u + s * STAGEB;
        #pragma unroll
        for (int i = 0; i < 2; i++) {
            int idx = tid + i * 256;
            int r   = idx >> 2;
            int cc  = idx & 3;
            uint32_t doff = (uint32_t)(r * RPADB + cc * 16);
            size_t  aoff  = (size_t)(cx.m0 + r) * rs + k0 + cc * 8;
            size_t  boff  = (size_t)(cx.n0 + r) * rs + k0 + cc * 8;
            cpa16(sb + 0 * ARRB + doff, sa_h + aoff);
            cpa16(sb + 1 * ARRB + doff, sa_l + aoff);
            cpa16(sb + 2 * ARRB + doff, sb_h + boff);
            cpa16(sb + 3 * ARRB + doff, sb_l + boff);
        }
    };

    issue_load(0, 0);
    CP_COMMIT();

    for (int c = 0; c < NCH_TOT; c++) {
        const int s = c & 1;
        if (c + 1 < NCH_TOT) { issue_load(c + 1, s ^ 1); CP_COMMIT(); CP_WAIT1(); }
        else                 { CP_WAIT0(); }
        __syncthreads();

        const uint32_t sb = smem_u + s * STAGEB;

        #pragma unroll
        for (int k16 = 0; k16 < KCH / 16; k16++) {
            uint32_t ah[2][4], al[2][4];
            #pragma unroll
            for (int mt = 0; mt < 2; mt++) {
                uint32_t ad = sb + (uint32_t)((wm * 32 + mt * 16 + aRow) * RPADB + k16 * 32 + aHalf * 16);
                ldm_x4(ah[mt], ad);
                ldm_x4(al[mt], ad + ARRB);
            }
            #pragma unroll
            for (int j = 0; j < 4; j++) {
                uint32_t bd = sb + 2 * ARRB +
                    (uint32_t)((wn * 64 + j * 16 + bN) * RPADB + k16 * 32 + bHalf * 16);
                uint32_t t0[4], t1[4];
                ldm_x4(t0, bd);
                ldm_x4(t1, bd + ARRB);
                uint32_t bh0[2] = { t0[0], t0[1] }, bh1[2] = { t0[2], t0[3] };
                uint32_t bl0[2] = { t1[0], t1[1] }, bl1[2] = { t1[2], t1[3] };
                #pragma unroll
                for (int mt = 0; mt < 2; mt++) {
                    mma_bf16(acc[mt][2 * j],     ah[mt], bh0);
                    mma_bf16(acc[mt][2 * j],     ah[mt], bl0);
                    mma_bf16(acc[mt][2 * j],     al[mt], bh0);
                    mma_bf16(acc[mt][2 * j + 1], ah[mt], bh1);
                    mma_bf16(acc[mt][2 * j + 1], ah[mt], bl1);
                    mma_bf16(acc[mt][2 * j + 1], al[mt], bh1);
                }
            }
        }
        __syncthreads();
    }
}

// ------------------------------------------- generic GEMM (proj): fp32 out
__global__ void __launch_bounds__(256, 2) mma_gemm(
    const bf16* __restrict__ Ah, const bf16* __restrict__ Al,
    const bf16* __restrict__ Wh, const bf16* __restrict__ Wl,
    const bf16* __restrict__ Hh, const bf16* __restrict__ Hl,
    const bf16* __restrict__ Blh, const bf16* __restrict__ Bll,
    float* __restrict__ C, int N, const int* __restrict__ experts, int estride)
{
    const int tid = threadIdx.x;
    const int lid = tid & 31;
    const int wid = tid >> 5;
    const int wm  = wid & 3;
    const int wn  = wid >> 2;
    const int g   = lid >> 2;
    const int q   = lid & 3;
    const int m0  = blockIdx.y * 128;
    const int n0  = blockIdx.x * 128;
    const int e   = expert_of(experts, (m0 % NSEQ) / CHUNK, estride);

    GemmCtx cx { Ah, Al, Wh, Wl, Hh, Hl,
                 Blh + (size_t)e * N * RR, Bll + (size_t)e * N * RR, m0, n0 };
    float acc[2][8][4] = {};
    gemm_mainloop_128(cx, tid, acc);

    #pragma unroll
    for (int mt = 0; mt < 2; mt++) {
        int row = m0 + wm * 32 + mt * 16 + g;
        #pragma unroll
        for (int nt = 0; nt < 8; nt++) {
            int col = n0 + wn * 64 + nt * 8 + q * 2;
            *(float2*)(C + (size_t)row * N + col) =
                make_float2(acc[mt][nt][0], acc[mt][nt][1]);
            *(float2*)(C + (size_t)(row + 8) * N + col) =
                make_float2(acc[mt][nt][2], acc[mt][nt][3]);
        }
    }
}

// ---------------------- QKV GEMM with fused attention-operand epilogue
// Writes Qh/Ql (scaled), Kh/Kl head-major; V via smem transpose -> Vth/Vtl.
__global__ void __launch_bounds__(256, 2) qkv_gemm(
    const bf16* __restrict__ Ah, const bf16* __restrict__ Al,
    const bf16* __restrict__ Wh, const bf16* __restrict__ Wl,
    const bf16* __restrict__ Hh, const bf16* __restrict__ Hl,
    const bf16* __restrict__ Blh, const bf16* __restrict__ Bll,
    bf16* __restrict__ Qh, bf16* __restrict__ Ql,
    bf16* __restrict__ Kh, bf16* __restrict__ Kl,
    bf16* __restrict__ Vth, bf16* __restrict__ Vtl,
    const int* __restrict__ experts, int estride)
{
    const int tid = threadIdx.x;
    const int lid = tid & 31;
    const int wid = tid >> 5;
    const int wm  = wid & 3;
    const int wn  = wid >> 2;
    const int g   = lid >> 2;
    const int q   = lid & 3;
    const int m0  = blockIdx.y * 128;
    const int n0  = blockIdx.x * 128;
    const int e   = expert_of(experts, (m0 % NSEQ) / CHUNK, estride);

    GemmCtx cx { Ah, Al, Wh, Wl, Hh, Hl,
                 Blh + (size_t)e * QKV_DIM * RR, Bll + (size_t)e * QKV_DIM * RR, m0, n0 };
    float acc[2][8][4] = {};
    gemm_mainloop_128(cx, tid, acc);

    const int seg = n0 / DIM;          // 0 Q, 1 K, 2 V
    const int nc0 = n0 % DIM;

    if (seg < 2) {
        const float sc = (seg == 0) ? (ATT_SCALE * LOG2E) : 1.0f;
        bf16* Dh = (seg == 0) ? Qh : Kh;
        bf16* Dl = (seg == 0) ? Ql : Kl;
        #pragma unroll
        for (int mt = 0; mt < 2; mt++) {
            #pragma unroll
            for (int half = 0; half < 2; half++) {
                int row = m0 + wm * 32 + mt * 16 + g + half * 8;
                int b = row >> 12, n = row & (NSEQ - 1);
                #pragma unroll
                for (int nt = 0; nt < 8; nt++) {
                    int c  = wn * 64 + nt * 8 + q * 2;
                    int nc = nc0 + c;
                    int hh = nc >> 6, d = nc & 63;
                    size_t dst = ((size_t)(b * HEADS + hh) * NSEQ + n) * HD + d;
                    float v0 = acc[mt][nt][half * 2 + 0] * sc;
                    float v1 = acc[mt][nt][half * 2 + 1] * sc;
                    *(uint32_t*)(Dh + dst) = pack2(v0, v1);
                    *(uint32_t*)(Dl + dst) = pack2lo(v0, v1);
                }
            }
        }
    } else {
        // stage fp32 into smem, transpose, write dim-major split V
        float* sm = (float*)dynsmem;
        #pragma unroll
        for (int mt = 0; mt < 2; mt++)
            #pragma unroll
            for (int half = 0; half < 2; half++) {
                int rl = wm * 32 + mt * 16 + g + half * 8;
                #pragma unroll
                for (int nt = 0; nt < 8; nt++) {
                    int c = wn * 64 + nt * 8 + q * 2;
                    sm[rl * VSTR + c]     = acc[mt][nt][half * 2 + 0];
                    sm[rl * VSTR + c + 1] = acc[mt][nt][half * 2 + 1];
                }
            }
        __syncthreads();

        const int bq = m0 >> 12;
        const int nbase = m0 & (NSEQ - 1);
        #pragma unroll
        for (int it = 0; it < 8; it++) {
            int idx = tid + it * 256;        // 0..2047
            int c   = idx >> 4;              // 0..127
            int tg  = idx & 15;              // token group of 8
            int nc  = nc0 + c;
            int hh  = nc >> 6, d = nc & 63;
            size_t dst = ((size_t)(bq * HEADS + hh) * HD + d) * NSEQ + nbase + tg * 8;
            float v[8];
            #pragma unroll
            for (int i = 0; i < 8; i++) v[i] = sm[(tg * 8 + i) * VSTR + c];
            uint4 whi, wlo;
            whi.x = pack2(v[0], v[1]); whi.y = pack2(v[2], v[3]);
            whi.z = pack2(v[4], v[5]); whi.w = pack2(v[6], v[7]);
            wlo.x = pack2lo(v[0], v[1]); wlo.y = pack2lo(v[2], v[3]);
            wlo.z = pack2lo(v[4], v[5]); wlo.w = pack2lo(v[6], v[7]);
            *(uint4*)(Vth + dst) = whi;
            *(uint4*)(Vtl + dst) = wlo;
        }
    }
}

// ------------------------------------------- HMMA LoRA-A: H = split(LSCALE * A @ Ae^T)
#define LARRA (128*RPADB)            // 10240
#define LARRB (64*RPADB)             // 5120
#define LSTG  (2*LARRA + 2*LARRB)    // 30720
#define LORA_SMEM (2*LSTG)           // 61440
#define LNCH  (DIM/KCH)              // 24

__global__ void __launch_bounds__(256, 1) lora_mma(
    const bf16* __restrict__ Ah, const bf16* __restrict__ Al,
    const bf16* __restrict__ Aeh, const bf16* __restrict__ Ael,
    bf16* __restrict__ Ch, bf16* __restrict__ Cl,
    const int* __restrict__ experts, int estride)
{
    const int tid = threadIdx.x;
    const int lid = tid & 31;
    const int wid = tid >> 5;
    const int g   = lid >> 2;
    const int q   = lid & 3;
    const int m0  = blockIdx.x * 128;
    const int e   = expert_of(experts, (m0 % NSEQ) / CHUNK, estride);

    const bf16* Beh = Aeh + (size_t)e * RR * DIM;
    const bf16* Bel = Ael + (size_t)e * RR * DIM;

    const uint32_t smem_u = s2u(dynsmem);
    const int aRow  = lid & 15;
    const int aHalf = lid >> 4;
    const int bN    = ((lid >> 4) & 1) * 8 + (lid & 7);
    const int bHalf = (lid >> 3) & 1;

    float acc[8][4] = {};

    auto issue_load = [&](int c, int s) {
        int k0 = c * KCH;
        uint32_t sb = smem_u + s * LSTG;
        #pragma unroll
        for (int i = 0; i < 2; i++) {
            int idx = tid + i * 256;
            int r = idx >> 2, cc = idx & 3;
            uint32_t doff = (uint32_t)(r * RPADB + cc * 16);
            size_t aoff = (size_t)(m0 + r) * DIM + k0 + cc * 8;
            cpa16(sb + doff,         Ah + aoff);
            cpa16(sb + LARRA + doff, Al + aoff);
        }
        {
            int r = tid >> 2, cc = tid & 3;
            if (r < 64) {
                uint32_t doff = (uint32_t)(r * RPADB + cc * 16);
                size_t boff = (size_t)r * DIM + k0 + cc * 8;
                cpa16(sb + 2 * LARRA + doff,         Beh + boff);
                cpa16(sb + 2 * LARRA + LARRB + doff, Bel + boff);
            }
        }
    };

    issue_load(0, 0);
    CP_COMMIT();

    for (int c = 0; c < LNCH; c++) {
        const int s = c & 1;
        if (c + 1 < LNCH) { issue_load(c + 1, s ^ 1); CP_COMMIT(); CP_WAIT1(); }
        else              { CP_WAIT0(); }
        __syncthreads();

        const uint32_t sb = smem_u + s * LSTG;
        #pragma unroll
        for (int k16 = 0; k16 < KCH / 16; k16++) {
            uint32_t ah[4], al[4];
            {
                uint32_t ad = sb + (uint32_t)((wid * 16 + aRow) * RPADB + k16 * 32 + aHalf * 16);
                ldm_x4(ah, ad);
                ldm_x4(al, ad + LARRA);
            }
            #pragma unroll
            for (int j = 0; j < 4; j++) {
                uint32_t bd = sb + 2 * LARRA +
                    (uint32_t)((j * 16 + bN) * RPADB + k16 * 32 + bHalf * 16);
                uint32_t t0[4], t1[4];
                ldm_x4(t0, bd);
                ldm_x4(t1, bd + LARRB);
                uint32_t bh0[2] = { t0[0], t0[1] }, bh1[2] = { t0[2], t0[3] };
                uint32_t bl0[2] = { t1[0], t1[1] }, bl1[2] = { t1[2], t1[3] };
                mma_bf16(acc[2 * j],     ah, bh0);
                mma_bf16(acc[2 * j],     ah, bl0);
                mma_bf16(acc[2 * j],     al, bh0);
                mma_bf16(acc[2 * j + 1], ah, bh1);
                mma_bf16(acc[2 * j + 1], ah, bl1);
                mma_bf16(acc[2 * j + 1], al, bh1);
            }
        }
        __syncthreads();
    }

    const int row0 = m0 + wid * 16 + g;
    #pragma unroll
    for (int nt = 0; nt < 8; nt++) {
        int col = nt * 8 + q * 2;
        #pragma unroll
        for (int half = 0; half < 2; half++) {
            int row = row0 + half * 8;
            float v0 = acc[nt][half * 2 + 0] * LSCALE;
            float v1 = acc[nt][half * 2 + 1] * LSCALE;
            *(uint32_t*)(Ch + (size_t)row * RR + col) = pack2(v0, v1);
            *(uint32_t*)(Cl + (size_t)row * RR + col) = pack2lo(v0, v1);
        }
    }
}

// ------------------------------------------ tensor-core flash attention
// Block: 128 q-rows, 8 warps (16 q-rows each), 64-key tiles, double-buffered.
// Epilogue writes oh/ol (bf16 hi/lo split) directly.
#define KSTR      72                  // row stride in bf16 elems (144B)
#define ATT_TILE  (64*KSTR*2)         // 9216 B per operand array
#define ATT_STAGE (4*ATT_TILE)        // kh | kl | vh | vl
#define ATT_SMEM  (2*ATT_STAGE)       // 73728

__global__ void __launch_bounds__(256, 1) attn_mma(
    const bf16* __restrict__ Qh, const bf16* __restrict__ Ql,
    const bf16* __restrict__ Kh, const bf16* __restrict__ Kl,
    const bf16* __restrict__ Vth, const bf16* __restrict__ Vtl,
    bf16* __restrict__ Oh, bf16* __restrict__ Ol)
{
    const int qt    = blockIdx.x;
    const int bh    = blockIdx.y;
    const int chunk = (NCHUNKS - 1) - blockIdx.z;   // heavy first
    const int b     = bh / HEADS, h = bh % HEADS;
    const int tid   = threadIdx.x;
    const int w     = tid >> 5, lid = tid & 31;
    const int g     = lid >> 2, q = lid & 3;
    const int klend = (chunk + 1) * CHUNK;

    const bf16* Qbh  = Qh  + (size_t)bh * NSEQ * HD;
    const bf16* Qlbh = Ql  + (size_t)bh * NSEQ * HD;
    const bf16* Kbh  = Kh  + (size_t)bh * NSEQ * HD;
    const bf16* Klbh = Kl  + (size_t)bh * NSEQ * HD;
    const bf16* Vbh  = Vth + (size_t)bh * HD * NSEQ;
    const bf16* Vlbh = Vtl + (size_t)bh * HD * NSEQ;

    const int r0 = chunk * CHUNK + qt * 128 + w * 16 + g;

    uint32_t qhf[4][4], qlf[4][4];
    #pragma unroll
    for (int kk = 0; kk < 4; kk++) {
        size_t base0 = (size_t)r0 * HD + kk * 16 + 2 * q;
        size_t base1 = (size_t)(r0 + 8) * HD + kk * 16 + 2 * q;
        qhf[kk][0] = *(const uint32_t*)(Qbh + base0);
        qhf[kk][1] = *(const uint32_t*)(Qbh + base1);
        qhf[kk][2] = *(const uint32_t*)(Qbh + base0 + 8);
        qhf[kk][3] = *(const uint32_t*)(Qbh + base1 + 8);
        qlf[kk][0] = *(const uint32_t*)(Qlbh + base0);
        qlf[kk][1] = *(const uint32_t*)(Qlbh + base1);
        qlf[kk][2] = *(const uint32_t*)(Qlbh + base0 + 8);
        qlf[kk][3] = *(const uint32_t*)(Qlbh + base1 + 8);
    }

    const uint32_t smem_u = s2u(dynsmem);
    const int bN    = ((lid >> 4) & 1) * 8 + (lid & 7);
    const int bHalf = (lid >> 3) & 1;

    float o[8][4] = {};
    float m0 = -1e30f, m1 = -1e30f, l0 = 0.f, l1 = 0.f;

    auto load_tile = [&](int kt, int s) {
        uint32_t base = smem_u + s * ATT_STAGE;
        #pragma unroll
        for (int i = 0; i < 2; i++) {
            int idx = tid + i * 256;
            int r = idx >> 3, c = idx & 7;
            uint32_t doff = (uint32_t)(r * KSTR + c * 8) * 2;
            cpa16(base + 0 * ATT_TILE + doff, Kbh  + (size_t)(kt + r) * HD + c * 8);
            cpa16(base + 1 * ATT_TILE + doff, Klbh + (size_t)(kt + r) * HD + c * 8);
            cpa16(base + 2 * ATT_TILE + doff, Vbh  + (size_t)r * NSEQ + kt + c * 8);
            cpa16(base + 3 * ATT_TILE + doff, Vlbh + (size_t)r * NSEQ + kt + c * 8);
        }
    };

    const int ntile = klend >> 6;
    load_tile(0, 0);
    CP_COMMIT();

    for (int t = 0; t < ntile; t++) {
        const int s = t & 1;
        if (t + 1 < ntile) { load_tile((t + 1) << 6, s ^ 1); CP_COMMIT(); CP_WAIT1(); }
        else               { CP_WAIT0(); }
        __syncthreads();

        const uint32_t sbK = smem_u + s * ATT_STAGE;
        const uint32_t sbV = sbK + 2 * ATT_TILE;

        // ---- scores S = Q.K^T (bf16x3)
        float sc[8][4] = {};
        #pragma unroll
        for (int kk = 0; kk < 4; kk++) {
            #pragma unroll
            for (int j = 0; j < 4; j++) {
                uint32_t kd = sbK + (uint32_t)((j * 16 + bN) * KSTR * 2 + kk * 32 + bHalf * 16);
                uint32_t t0[4], t1[4];
                ldm_x4(t0, kd);
                ldm_x4(t1, kd + ATT_TILE);
                uint32_t kb0[2] = { t0[0], t0[1] }, kb1[2] = { t0[2], t0[3] };
                uint32_t kl0[2] = { t1[0], t1[1] }, kl1[2] = { t1[2], t1[3] };
                mma_bf16(sc[2 * j],     qhf[kk], kb0);
                mma_bf16(sc[2 * j],     qhf[kk], kl0);
                mma_bf16(sc[2 * j],     qlf[kk], kb0);
                mma_bf16(sc[2 * j + 1], qhf[kk], kb1);
                mma_bf16(sc[2 * j + 1], qhf[kk], kl1);
                mma_bf16(sc[2 * j + 1], qlf[kk], kb1);
            }
        }

        // ---- online softmax (exp2 domain)
        float mt0 = -1e30f, mt1 = -1e30f;
        #pragma unroll
        for (int nt = 0; nt < 8; nt++) {
            mt0 = fmaxf(mt0, fmaxf(sc[nt][0], sc[nt][1]));
            mt1 = fmaxf(mt1, fmaxf(sc[nt][2], sc[nt][3]));
        }
        mt0 = fmaxf(mt0, __shfl_xor_sync(0xffffffffu, mt0, 1));
        mt0 = fmaxf(mt0, __shfl_xor_sync(0xffffffffu, mt0, 2));
        mt1 = fmaxf(mt1, __shfl_xor_sync(0xffffffffu, mt1, 1));
        mt1 = fmaxf(mt1, __shfl_xor_sync(0xffffffffu, mt1, 2));

        float mn0 = fmaxf(m0, mt0), mn1 = fmaxf(m1, mt1);
        float c0 = ex2f(m0 - mn0), c1 = ex2f(m1 - mn1);
        m0 = mn0; m1 = mn1;
        l0 *= c0; l1 *= c1;

        uint32_t pha[4][4], pla[4][4];
        #pragma unroll
        for (int nt = 0; nt < 8; nt++) {
            float p0 = ex2f(sc[nt][0] - m0);
            float p1 = ex2f(sc[nt][1] - m0);
            float p2 = ex2f(sc[nt][2] - m1);
            float p3 = ex2f(sc[nt][3] - m1);
            l0 += p0 + p1;
            l1 += p2 + p3;
            int kk = nt >> 1, hf = nt & 1;
            pha[kk][hf * 2 + 0] = pack2(p0, p1);
            pha[kk][hf * 2 + 1] = pack2(p2, p3);
            pla[kk][hf * 2 + 0] = pack2lo(p0, p1);
            pla[kk][hf * 2 + 1] = pack2lo(p2, p3);
        }

        #pragma unroll
        for (int nt = 0; nt < 8; nt++) {
            o[nt][0] *= c0; o[nt][1] *= c0;
            o[nt][2] *= c1; o[nt][3] *= c1;
        }

        // ---- O += P.V (bf16x3)
        #pragma unroll
        for (int kk = 0; kk < 4; kk++) {
            #pragma unroll
            for (int j = 0; j < 4; j++) {
                uint32_t vd = sbV + (uint32_t)((j * 16 + bN) * KSTR * 2 + kk * 32 + bHalf * 16);
                uint32_t t0[4], t1[4];
                ldm_x4(t0, vd);
                ldm_x4(t1, vd + ATT_TILE);
                uint32_t vb0[2] = { t0[0], t0[1] }, vb1[2] = { t0[2], t0[3] };
                uint32_t vl0[2] = { t1[0], t1[1] }, vl1[2] = { t1[2], t1[3] };
                mma_bf16(o[2 * j],     pha[kk], vb0);
                mma_bf16(o[2 * j],     pha[kk], vl0);
                mma_bf16(o[2 * j],     pla[kk], vb0);
                mma_bf16(o[2 * j + 1], pha[kk], vb1);
                mma_bf16(o[2 * j + 1], pha[kk], vl1);
                mma_bf16(o[2 * j + 1], pla[kk], vb1);
            }
        }
        __syncthreads();
    }

    // ---- finalize: write split o directly
    l0 += __shfl_xor_sync(0xffffffffu, l0, 1);
    l0 += __shfl_xor_sync(0xffffffffu, l0, 2);
    l1 += __shfl_xor_sync(0xffffffffu, l1, 1);
    l1 += __shfl_xor_sync(0xffffffffu, l1, 2);
    const float inv0 = 1.0f / l0, inv1 = 1.0f / l1;

    size_t off0 = ((size_t)(b * NSEQ + r0)) * DIM + h * HD;
    size_t off1 = ((size_t)(b * NSEQ + r0 + 8)) * DIM + h * HD;
    #pragma unroll
    for (int nt = 0; nt < 8; nt++) {
        int col = nt * 8 + 2 * q;
        float a0 = o[nt][0] * inv0, a1 = o[nt][1] * inv0;
        float b0 = o[nt][2] * inv1, b1 = o[nt][3] * inv1;
        *(uint32_t*)(Oh + off0 + col) = pack2(a0, a1);
        *(uint32_t*)(Ol + off0 + col) = pack2lo(a0, a1);
        *(uint32_t*)(Oh + off1 + col) = pack2(b0, b1);
        *(uint32_t*)(Ol + off1 + col) = pack2lo(b0, b1);
    }
}

// ------------------------------------------------------------------- launch
static inline void run_split(const float* src, bf16* hi, bf16* lo, size_t n) {
    int n4 = (int)(n / 4);
    split_kernel<<<(n4 + 255) / 256, 256>>>(src, hi, lo, n4);
}

extern "C" void kernel_launch(void* const* d_in, const int* in_sizes, int n_in,
                              void* d_out, int out_size)
{
    const float* x       = (const float*)d_in[0];
    const float* Wqkv    = (const float*)d_in[1];
    const float* Aqkv    = (const float*)d_in[2];
    const float* Bqkv    = (const float*)d_in[3];
    const float* Wproj   = (const float*)d_in[4];
    const float* Aproj   = (const float*)d_in[5];
    const float* Bproj   = (const float*)d_in[6];
    const int*   experts = (const int*)d_in[7];
    float*       out     = (float*)d_out;

    int estride = (in_sizes[7] >= 2 * NCHUNKS) ? 2 : 1;

    bf16 *xh, *xl, *oh, *ol, *wqh, *wql, *wph, *wpl;
    bf16 *bqh, *bql, *bph, *bpl, *aqh, *aql, *aph, *apl, *hh, *hl;
    bf16 *qah, *qal, *kah, *kal, *vth, *vtl;
    cudaGetSymbolAddress((void**)&xh,  g_xh);  cudaGetSymbolAddress((void**)&xl,  g_xl);
    cudaGetSymbolAddress((void**)&oh,  g_oh);  cudaGetSymbolAddress((void**)&ol,  g_ol);
    cudaGetSymbolAddress((void**)&wqh, g_wqh); cudaGetSymbolAddress((void**)&wql, g_wql);
    cudaGetSymbolAddress((void**)&wph, g_wph); cudaGetSymbolAddress((void**)&wpl, g_wpl);
    cudaGetSymbolAddress((void**)&bqh, g_bqh); cudaGetSymbolAddress((void**)&bql, g_bql);
    cudaGetSymbolAddress((void**)&bph, g_bph); cudaGetSymbolAddress((void**)&bpl, g_bpl);
    cudaGetSymbolAddress((void**)&aqh, g_aqh); cudaGetSymbolAddress((void**)&aql, g_aql);
    cudaGetSymbolAddress((void**)&aph, g_aph); cudaGetSymbolAddress((void**)&apl, g_apl);
    cudaGetSymbolAddress((void**)&hh,  g_hh);  cudaGetSymbolAddress((void**)&hl,  g_hl);
    cudaGetSymbolAddress((void**)&qah, g_qah); cudaGetSymbolAddress((void**)&qal, g_qal);
    cudaGetSymbolAddress((void**)&kah, g_kah); cudaGetSymbolAddress((void**)&kal, g_kal);
    cudaGetSymbolAddress((void**)&vth, g_vth); cudaGetSymbolAddress((void**)&vtl, g_vtl);

    cudaFuncSetAttribute(mma_gemm, cudaFuncAttributeMaxDynamicSharedMemorySize, MMG_SMEM);
    cudaFuncSetAttribute(qkv_gemm, cudaFuncAttributeMaxDynamicSharedMemorySize, MMG_SMEM);
    cudaFuncSetAttribute(lora_mma, cudaFuncAttributeMaxDynamicSharedMemorySize, LORA_SMEM);
    cudaFuncSetAttribute(attn_mma, cudaFuncAttributeMaxDynamicSharedMemorySize, ATT_SMEM);

    // 0) split fp32 operands into bf16 hi/lo
    run_split(x,     xh,  xl,  (size_t)TOKENS * DIM);
    run_split(Wqkv,  wqh, wql, (size_t)QKV_DIM * DIM);
    run_split(Bqkv,  bqh, bql, (size_t)NEXP * QKV_DIM * RR);
    run_split(Wproj, wph, wpl, (size_t)DIM * DIM);
    run_split(Bproj, bph, bpl, (size_t)NEXP * DIM * RR);
    run_split(Aqkv,  aqh, aql, (size_t)NEXP * RR * DIM);
    run_split(Aproj, aph, apl, (size_t)NEXP * RR * DIM);

    // 1) H = split(LSCALE * x @ Aqkv[e]^T)
    lora_mma<<<TOKENS / 128, 256, LORA_SMEM>>>(xh, xl, aqh, aql, hh, hl, experts, estride);

    // 2) QKV GEMM with fused attention-operand epilogue
    {
        dim3 grid(QKV_DIM / 128, TOKENS / 128);
        qkv_gemm<<<grid, 256, MMG_SMEM>>>(xh, xl, wqh, wql, hh, hl, bqh, bql,
                                          qah, qal, kah, kal, vth, vtl,
                                          experts, estride);
    }

    // 3) tensor-core chunked block-causal attention (writes split o)
    {
        dim3 grid(CHUNK / 128, BB * HEADS, NCHUNKS);
        attn_mma<<<grid, 256, ATT_SMEM>>>(qah, qal, kah, kal, vth, vtl, oh, ol);
    }

    // 4) H2 = split(LSCALE * o @ Aproj[e]^T)
    lora_mma<<<TOKENS / 128, 256, LORA_SMEM>>>(oh, ol, aph, apl, hh, hl, experts, estride);

    // 5) out = o @ Wproj^T + H2 @ Bproj[e]^T
    {
        dim3 grid(DIM / 128, TOKENS / 128);
        mma_gemm<<<grid, 256, MMG_SMEM>>>(oh, ol, wph, wpl, hh, hl, bph, bpl,
                                          out, DIM, experts, estride);
    }
}